// round 4
// baseline (speedup 1.0000x reference)
#include <cuda_runtime.h>
#include <cuda_bf16.h>
#include <cstdint>

#define BATCH 4
#define T 2048
#define C 1024
#define H 64
#define M_TOTAL (BATCH * T)   // 8192
#define NSPLIT 2

// Scratch (allocation-free rule: __device__ globals)
__device__ float g_q[BATCH * T * H];
__device__ float g_k[BATCH * T * H];
__device__ float g_v[BATCH * T * H];
__device__ float g_opart[NSPLIT][BATCH * T * H];
__device__ float g_m[NSPLIT][BATCH * T];
__device__ float g_l[NSPLIT][BATCH * T];
__device__ __nv_bfloat16 g_wh[192 * C];   // [Wq;Wk;Wv] bf16 hi
__device__ __nv_bfloat16 g_wl[192 * C];   // bf16 lo (residual)

// ===========================================================================
// Helpers (portable sm_80+ tensor path: mma.sync / ldmatrix / cp.async)
// ===========================================================================
__device__ __forceinline__ uint32_t smem_to_u32(const void* p) {
    uint32_t a;
    asm("{ .reg .u64 t; cvta.to.shared.u64 t, %1; cvt.u32.u64 %0, t; }" : "=r"(a) : "l"(p));
    return a;
}
__device__ __forceinline__ void ldsm4(uint32_t* r, uint32_t addr) {
    asm volatile("ldmatrix.sync.aligned.m8n8.x4.shared.b16 {%0,%1,%2,%3}, [%4];"
                 : "=r"(r[0]), "=r"(r[1]), "=r"(r[2]), "=r"(r[3]) : "r"(addr));
}
__device__ __forceinline__ void mma16816(float* d, const uint32_t* a, const uint32_t* b) {
    asm volatile(
        "mma.sync.aligned.m16n8k16.row.col.f32.bf16.bf16.f32 "
        "{%0,%1,%2,%3}, {%4,%5,%6,%7}, {%8,%9}, {%0,%1,%2,%3};"
        : "+f"(d[0]), "+f"(d[1]), "+f"(d[2]), "+f"(d[3])
        : "r"(a[0]), "r"(a[1]), "r"(a[2]), "r"(a[3]), "r"(b[0]), "r"(b[1]));
}
__device__ __forceinline__ void cp16(uint32_t smem_addr, const void* gptr) {
    asm volatile("cp.async.cg.shared.global [%0], [%1], 16;" :: "r"(smem_addr), "l"(gptr));
}
__device__ __forceinline__ void cp_commit() { asm volatile("cp.async.commit_group;" ::: "memory"); }
__device__ __forceinline__ void cp_wait0()  { asm volatile("cp.async.wait_group 0;" ::: "memory"); }

// bf16 hi/lo split of two floats, packed as bf16x2 words
__device__ __forceinline__ void split2(float a, float b, uint32_t& hi, uint32_t& lo) {
    __nv_bfloat16 ha = __float2bfloat16_rn(a);
    __nv_bfloat16 hb = __float2bfloat16_rn(b);
    float ra = a - __bfloat162float(ha);
    float rb = b - __bfloat162float(hb);
    __nv_bfloat16 la = __float2bfloat16_rn(ra);
    __nv_bfloat16 lb = __float2bfloat16_rn(rb);
    hi = (uint32_t)__bfloat16_as_ushort(ha) | ((uint32_t)__bfloat16_as_ushort(hb) << 16);
    lo = (uint32_t)__bfloat16_as_ushort(la) | ((uint32_t)__bfloat16_as_ushort(lb) << 16);
}

// ===========================================================================
// W -> bf16 hi/lo (run once, tiny)
// ===========================================================================
__global__ __launch_bounds__(256) void wconv_kernel(
    const float* __restrict__ Wq, const float* __restrict__ Wk, const float* __restrict__ Wv)
{
    int idx = blockIdx.x * 256 + threadIdx.x;     // float4 units, 192*256 total
    int r = idx >> 8;                             // 0..191
    int c = idx & 255;                            // float4 within row
    const float* W = (r < 64) ? Wq : ((r < 128) ? Wk : Wv);
    int rr = r & 63;
    float4 w = *(const float4*)(W + (size_t)rr * C + c * 4);
    uint32_t h0, l0, h1, l1;
    split2(w.x, w.y, h0, l0);
    split2(w.z, w.w, h1, l1);
    *(uint2*)&g_wh[(size_t)r * C + c * 4] = make_uint2(h0, h1);
    *(uint2*)&g_wl[(size_t)r * C + c * 4] = make_uint2(l0, l1);
}

// ===========================================================================
// Projection via mma.sync bf16x3: out[m][h] = sum_c x[m][c]*W[h][c]
// Per CTA: BM=128, one head (N=64). K-chunks of 32, double-buffered SMEM.
// 8 warps, warp tile M16 x N64 (8 n-frags). A converted fp32->bf16 inline.
// SMEM rows padded to 80B -> conflict-free ldmatrix.
// ===========================================================================
// SMEM layout (bytes): Ah[2][10240] @0, Al[2][10240] @20480,
//                      Bh[2][5120] @40960, Bl[2][5120] @51200  -> 61440
#define OFF_AH 0
#define OFF_AL 20480
#define OFF_BH 40960
#define OFF_BL 51200
#define PROJ_SMEM 61440
#define NIT 32   // 1024/32

__global__ __launch_bounds__(256) void proj_mma_kernel(const float* __restrict__ x)
{
    extern __shared__ char sm[];
    const uint32_t sb = smem_to_u32(sm);
    const int tid  = threadIdx.x;
    const int wid  = tid >> 5;
    const int lane = tid & 31;
    const int j    = blockIdx.y;
    const int mblk = blockIdx.x * 128;

    float* outp = (j == 0) ? g_q : ((j == 1) ? g_k : g_v);
    const __nv_bfloat16* whb = g_wh + (size_t)j * 64 * C;
    const __nv_bfloat16* wlb = g_wl + (size_t)j * 64 * C;

    float acc[8][4] = {};

    // A loader mapping: 4 float4/thread/iter
    const int arow = tid >> 3;        // 0..31 (+ i*32)
    const int ac4  = tid & 7;         // float4 within 32-float row chunk
    // B loader mapping: 1x16B per matrix per thread
    const int brow = tid >> 2;        // 0..63
    const int bc   = tid & 3;         // 16B chunk within 64B row

    // ---- prologue: A(0) -> regs -> SMEM[0];  B(0) -> cp.async into [0]
    float4 areg[4];
    #pragma unroll
    for (int i = 0; i < 4; i++)
        areg[i] = *(const float4*)(x + (size_t)(mblk + arow + i * 32) * C + ac4 * 4);
    #pragma unroll
    for (int i = 0; i < 4; i++) {
        uint32_t h0, l0, h1, l1;
        split2(areg[i].x, areg[i].y, h0, l0);
        split2(areg[i].z, areg[i].w, h1, l1);
        int row = arow + i * 32;
        *(uint2*)(sm + OFF_AH + row * 80 + ac4 * 8) = make_uint2(h0, h1);
        *(uint2*)(sm + OFF_AL + row * 80 + ac4 * 8) = make_uint2(l0, l1);
    }
    cp16(sb + OFF_BH + brow * 80 + bc * 16, whb + (size_t)brow * C + bc * 8);
    cp16(sb + OFF_BL + brow * 80 + bc * 16, wlb + (size_t)brow * C + bc * 8);
    cp_commit();

    const int l7  = lane & 7;
    const int lb3 = (lane >> 3) & 1;
    const int lb4 = (lane >> 4) & 1;

    for (int it = 0; it < NIT; it++) {
        const int p = it & 1;
        const int q = 1 - p;

        if (it + 1 < NIT) {
            const int k0n = (it + 1) * 32;
            #pragma unroll
            for (int i = 0; i < 4; i++)
                areg[i] = *(const float4*)(x + (size_t)(mblk + arow + i * 32) * C + k0n + ac4 * 4);
        }

        cp_wait0();
        __syncthreads();

        if (it + 1 < NIT) {
            const int k0n = (it + 1) * 32;
            cp16(sb + OFF_BH + q * 5120 + brow * 80 + bc * 16, whb + (size_t)brow * C + k0n + bc * 8);
            cp16(sb + OFF_BL + q * 5120 + brow * 80 + bc * 16, wlb + (size_t)brow * C + k0n + bc * 8);
            cp_commit();
        }

        // ---- compute chunk it from buffers [p]
        const uint32_t baseAh = sb + OFF_AH + p * 10240;
        const uint32_t baseAl = sb + OFF_AL + p * 10240;
        const uint32_t baseBh = sb + OFF_BH + p * 5120;
        const uint32_t baseBl = sb + OFF_BL + p * 5120;

        #pragma unroll
        for (int ks = 0; ks < 2; ks++) {
            const uint32_t aoff = (uint32_t)(wid * 16 + lb3 * 8 + l7) * 80 + (ks * 16 + lb4 * 8) * 2;
            uint32_t ah[4], al[4];
            ldsm4(ah, baseAh + aoff);
            ldsm4(al, baseAl + aoff);

            uint32_t bh[16], bl[16];
            #pragma unroll
            for (int t = 0; t < 4; t++) {
                const uint32_t boff = (uint32_t)(t * 16 + lb4 * 8 + l7) * 80 + (ks * 16 + lb3 * 8) * 2;
                ldsm4(&bh[t * 4], baseBh + boff);
                ldsm4(&bl[t * 4], baseBl + boff);
            }
            #pragma unroll
            for (int t = 0; t < 4; t++) {
                #pragma unroll
                for (int s2 = 0; s2 < 2; s2++) {
                    const int nt = t * 2 + s2;
                    mma16816(acc[nt], ah, &bh[t * 4 + s2 * 2]);
                    mma16816(acc[nt], ah, &bl[t * 4 + s2 * 2]);
                    mma16816(acc[nt], al, &bh[t * 4 + s2 * 2]);
                }
            }
        }

        if (it + 1 < NIT) {
            #pragma unroll
            for (int i = 0; i < 4; i++) {
                uint32_t h0, l0, h1, l1;
                split2(areg[i].x, areg[i].y, h0, l0);
                split2(areg[i].z, areg[i].w, h1, l1);
                int row = arow + i * 32;
                *(uint2*)(sm + OFF_AH + q * 10240 + row * 80 + ac4 * 8) = make_uint2(h0, h1);
                *(uint2*)(sm + OFF_AL + q * 10240 + row * 80 + ac4 * 8) = make_uint2(l0, l1);
            }
        }
    }

    // ---- epilogue
    const int g   = lane >> 2;
    const int tig = lane & 3;
    const int m1  = mblk + wid * 16 + g;
    #pragma unroll
    for (int nt = 0; nt < 8; nt++) {
        const int h = nt * 8 + tig * 2;
        *(float2*)(outp + (size_t)m1 * H + h)       = make_float2(acc[nt][0], acc[nt][1]);
        *(float2*)(outp + (size_t)(m1 + 8) * H + h) = make_float2(acc[nt][2], acc[nt][3]);
    }
}

// ===========================================================================
// Flash attention partial (fp32 CUDA cores) — unchanged (known-good)
// ===========================================================================
__global__ __launch_bounds__(256) void attn_kernel()
{
    __shared__ float Qs[64 * 32];
    __shared__ float KP[64 * 68];
    __shared__ float Vs[64 * 68];

    const int tid = threadIdx.x;
    const int tm  = tid >> 4;
    const int tn  = tid & 15;
    const int m0  = tm * 2;
    const int c0  = tn * 4;
    const int b   = blockIdx.y;
    const int qt  = (T / 32 - 1) - blockIdx.x;
    const int sp  = blockIdx.z;
    const int q0  = qt * 32;

    const int kt_last = (q0 + 31) >> 6;
    const int ntiles  = kt_last + 1;
    const int mid     = (ntiles + 1) >> 1;
    const int kt_beg  = (sp == 0) ? 0   : mid;
    const int kt_end  = (sp == 0) ? mid : ntiles;

    const int r_base = b * T + q0;

    if (kt_beg >= kt_end) {
        #pragma unroll
        for (int i = 0; i < 2; i++) {
            *(float4*)&g_opart[sp][(size_t)(r_base + m0 + i) * H + c0] =
                make_float4(0.f, 0.f, 0.f, 0.f);
            if (tn == 0) {
                g_m[sp][r_base + m0 + i] = -1e30f;
                g_l[sp][r_base + m0 + i] = 0.f;
            }
        }
        return;
    }

    const float* qg = g_q + (size_t)b * T * H;
    const float* kg = g_k + (size_t)b * T * H;
    const float* vg = g_v + (size_t)b * T * H;

    #pragma unroll
    for (int i = 0; i < 2; i++) {
        int idx = i * 256 + tid;
        int m  = idx >> 4;
        int hq = idx & 15;
        float4 a = *(const float4*)(qg + (size_t)(q0 + m) * H + hq * 4);
        Qs[(hq * 4 + 0) * 32 + m] = a.x * 0.125f;
        Qs[(hq * 4 + 1) * 32 + m] = a.y * 0.125f;
        Qs[(hq * 4 + 2) * 32 + m] = a.z * 0.125f;
        Qs[(hq * 4 + 3) * 32 + m] = a.w * 0.125f;
    }

    float o[2][4]  = {};
    float run_m[2] = {-1e30f, -1e30f};
    float run_l[2] = {0.f, 0.f};

    for (int kt = kt_beg; kt < kt_end; kt++) {
        const int k0 = kt * 64;
        __syncthreads();

        #pragma unroll
        for (int i = 0; i < 4; i++) {
            int idx = i * 256 + tid;
            int n  = idx >> 4;
            int hq = idx & 15;
            float4 ka = *(const float4*)(kg + (size_t)(k0 + n) * H + hq * 4);
            KP[(hq * 4 + 0) * 68 + n] = ka.x;
            KP[(hq * 4 + 1) * 68 + n] = ka.y;
            KP[(hq * 4 + 2) * 68 + n] = ka.z;
            KP[(hq * 4 + 3) * 68 + n] = ka.w;
            float4 va = *(const float4*)(vg + (size_t)(k0 + n) * H + hq * 4);
            *(float4*)&Vs[n * 68 + hq * 4] = va;
        }
        __syncthreads();

        float s[2][4] = {};
        #pragma unroll
        for (int h = 0; h < 64; h++) {
            float2 a  = *(const float2*)&Qs[h * 32 + m0];
            float4 bk = *(const float4*)&KP[h * 68 + c0];
            s[0][0] += a.x * bk.x; s[0][1] += a.x * bk.y; s[0][2] += a.x * bk.z; s[0][3] += a.x * bk.w;
            s[1][0] += a.y * bk.x; s[1][1] += a.y * bk.y; s[1][2] += a.y * bk.z; s[1][3] += a.y * bk.w;
        }

        if (kt == kt_last) {
            #pragma unroll
            for (int i = 0; i < 2; i++)
                #pragma unroll
                for (int jj = 0; jj < 4; jj++)
                    if (k0 + c0 + jj > q0 + m0 + i) s[i][jj] = -1e30f;
        }

        #pragma unroll
        for (int i = 0; i < 2; i++) {
            float pm = fmaxf(fmaxf(s[i][0], s[i][1]), fmaxf(s[i][2], s[i][3]));
            pm = fmaxf(pm, __shfl_xor_sync(0xffffffffu, pm, 1));
            pm = fmaxf(pm, __shfl_xor_sync(0xffffffffu, pm, 2));
            pm = fmaxf(pm, __shfl_xor_sync(0xffffffffu, pm, 4));
            pm = fmaxf(pm, __shfl_xor_sync(0xffffffffu, pm, 8));
            float nm    = fmaxf(run_m[i], pm);
            float alpha = __expf(run_m[i] - nm);
            float rs = 0.f;
            #pragma unroll
            for (int jj = 0; jj < 4; jj++) {
                s[i][jj] = __expf(s[i][jj] - nm);
                rs += s[i][jj];
            }
            rs += __shfl_xor_sync(0xffffffffu, rs, 1);
            rs += __shfl_xor_sync(0xffffffffu, rs, 2);
            rs += __shfl_xor_sync(0xffffffffu, rs, 4);
            rs += __shfl_xor_sync(0xffffffffu, rs, 8);
            run_l[i] = run_l[i] * alpha + rs;
            run_m[i] = nm;
            #pragma unroll
            for (int jj = 0; jj < 4; jj++) o[i][jj] *= alpha;
        }

        __syncthreads();

        #pragma unroll
        for (int i = 0; i < 2; i++)
            #pragma unroll
            for (int jj = 0; jj < 4; jj++)
                KP[(c0 + jj) * 66 + m0 + i] = s[i][jj];
        __syncthreads();

        #pragma unroll
        for (int n = 0; n < 64; n++) {
            float2 p  = *(const float2*)&KP[n * 66 + m0];
            float4 vv = *(const float4*)&Vs[n * 68 + c0];
            o[0][0] += p.x * vv.x; o[0][1] += p.x * vv.y; o[0][2] += p.x * vv.z; o[0][3] += p.x * vv.w;
            o[1][0] += p.y * vv.x; o[1][1] += p.y * vv.y; o[1][2] += p.y * vv.z; o[1][3] += p.y * vv.w;
        }
    }

    #pragma unroll
    for (int i = 0; i < 2; i++) {
        *(float4*)&g_opart[sp][(size_t)(r_base + m0 + i) * H + c0] =
            make_float4(o[i][0], o[i][1], o[i][2], o[i][3]);
        if (tn == 0) {
            g_m[sp][r_base + m0 + i] = run_m[i];
            g_l[sp][r_base + m0 + i] = run_l[i];
        }
    }
}

// ===========================================================================
// Combine partials
// ===========================================================================
__global__ __launch_bounds__(256) void combine_kernel(float* __restrict__ out)
{
    int idx = blockIdx.x * 256 + threadIdx.x;
    int row = idx >> 4;
    int c4  = (idx & 15) * 4;

    float m1 = g_m[0][row], m2 = g_m[1][row];
    float l1 = g_l[0][row], l2 = g_l[1][row];
    float M  = fmaxf(m1, m2);
    float w1 = __expf(m1 - M);
    float w2 = __expf(m2 - M);
    float inv = 1.0f / (w1 * l1 + w2 * l2);

    float4 o1 = *(const float4*)&g_opart[0][(size_t)row * H + c4];
    float4 o2 = *(const float4*)&g_opart[1][(size_t)row * H + c4];
    float4 r;
    r.x = (w1 * o1.x + w2 * o2.x) * inv;
    r.y = (w1 * o1.y + w2 * o2.y) * inv;
    r.z = (w1 * o1.z + w2 * o2.z) * inv;
    r.w = (w1 * o1.w + w2 * o2.w) * inv;
    *(float4*)&out[(size_t)row * H + c4] = r;
}

// ===========================================================================
extern "C" void kernel_launch(void* const* d_in, const int* in_sizes, int n_in,
                              void* d_out, int out_size)
{
    const float* x  = (const float*)d_in[0];
    const float* Wq = (const float*)d_in[1];
    const float* Wk = (const float*)d_in[2];
    const float* Wv = (const float*)d_in[3];
    float* out = (float*)d_out;

    cudaFuncSetAttribute(proj_mma_kernel,
                         cudaFuncAttributeMaxDynamicSharedMemorySize, PROJ_SMEM);

    wconv_kernel<<<192, 256>>>(Wq, Wk, Wv);
    proj_mma_kernel<<<dim3(M_TOTAL / 128, 3), 256, PROJ_SMEM>>>(x);
    attn_kernel<<<dim3(T / 32, BATCH, NSPLIT), 256>>>();
    combine_kernel<<<(M_TOTAL * (H / 4)) / 256, 256>>>(out);
}

// round 5
// speedup vs baseline: 1.0111x; 1.0111x over previous
#include <cuda_runtime.h>
#include <cuda_bf16.h>
#include <cstdint>

#define BATCH 4
#define T 2048
#define C 1024
#define H 64
#define M_TOTAL (BATCH * T)   // 8192
#define NSPLIT 2

// Scratch (allocation-free rule: __device__ globals)
__device__ float g_q[BATCH * T * H];
__device__ float g_k[BATCH * T * H];
__device__ float g_v[BATCH * T * H];
__device__ float g_opart[NSPLIT][BATCH * T * H];
__device__ float g_m[NSPLIT][BATCH * T];
__device__ float g_l[NSPLIT][BATCH * T];
__device__ __nv_bfloat16 g_xh[M_TOTAL * C];   // x bf16 hi
__device__ __nv_bfloat16 g_xl[M_TOTAL * C];   // x bf16 lo (residual)
__device__ __nv_bfloat16 g_wh[192 * C];       // [Wq;Wk;Wv] bf16 hi
__device__ __nv_bfloat16 g_wl[192 * C];       // bf16 lo

// ===========================================================================
// Helpers (portable sm_80+ tensor path)
// ===========================================================================
__device__ __forceinline__ uint32_t smem_to_u32(const void* p) {
    uint32_t a;
    asm("{ .reg .u64 t; cvta.to.shared.u64 t, %1; cvt.u32.u64 %0, t; }" : "=r"(a) : "l"(p));
    return a;
}
__device__ __forceinline__ void ldsm4(uint32_t* r, uint32_t addr) {
    asm volatile("ldmatrix.sync.aligned.m8n8.x4.shared.b16 {%0,%1,%2,%3}, [%4];"
                 : "=r"(r[0]), "=r"(r[1]), "=r"(r[2]), "=r"(r[3]) : "r"(addr));
}
__device__ __forceinline__ void mma16816(float* d, const uint32_t* a, const uint32_t* b) {
    asm volatile(
        "mma.sync.aligned.m16n8k16.row.col.f32.bf16.bf16.f32 "
        "{%0,%1,%2,%3}, {%4,%5,%6,%7}, {%8,%9}, {%0,%1,%2,%3};"
        : "+f"(d[0]), "+f"(d[1]), "+f"(d[2]), "+f"(d[3])
        : "r"(a[0]), "r"(a[1]), "r"(a[2]), "r"(a[3]), "r"(b[0]), "r"(b[1]));
}
__device__ __forceinline__ void cp16(uint32_t smem_addr, const void* gptr) {
    asm volatile("cp.async.cg.shared.global [%0], [%1], 16;" :: "r"(smem_addr), "l"(gptr));
}
__device__ __forceinline__ void cp_commit() { asm volatile("cp.async.commit_group;" ::: "memory"); }
template <int N>
__device__ __forceinline__ void cp_wait() {
    asm volatile("cp.async.wait_group %0;" :: "n"(N) : "memory");
}

__device__ __forceinline__ void split2(float a, float b, uint32_t& hi, uint32_t& lo) {
    __nv_bfloat16 ha = __float2bfloat16_rn(a);
    __nv_bfloat16 hb = __float2bfloat16_rn(b);
    float ra = a - __bfloat162float(ha);
    float rb = b - __bfloat162float(hb);
    __nv_bfloat16 la = __float2bfloat16_rn(ra);
    __nv_bfloat16 lb = __float2bfloat16_rn(rb);
    hi = (uint32_t)__bfloat16_as_ushort(ha) | ((uint32_t)__bfloat16_as_ushort(hb) << 16);
    lo = (uint32_t)__bfloat16_as_ushort(la) | ((uint32_t)__bfloat16_as_ushort(lb) << 16);
}

// ===========================================================================
// x -> bf16 hi/lo  (memory-bound, once)
// ===========================================================================
__global__ __launch_bounds__(256) void xconv_kernel(const float* __restrict__ x)
{
    size_t idx = (size_t)blockIdx.x * 256 + threadIdx.x;   // float4 units
    float4 v = *(const float4*)(x + idx * 4);
    uint32_t h0, l0, h1, l1;
    split2(v.x, v.y, h0, l0);
    split2(v.z, v.w, h1, l1);
    *(uint2*)&g_xh[idx * 4] = make_uint2(h0, h1);
    *(uint2*)&g_xl[idx * 4] = make_uint2(l0, l1);
}

// ===========================================================================
// W -> bf16 hi/lo (tiny)
// ===========================================================================
__global__ __launch_bounds__(256) void wconv_kernel(
    const float* __restrict__ Wq, const float* __restrict__ Wk, const float* __restrict__ Wv)
{
    int idx = blockIdx.x * 256 + threadIdx.x;
    int r = idx >> 8;
    int c = idx & 255;
    const float* W = (r < 64) ? Wq : ((r < 128) ? Wk : Wv);
    int rr = r & 63;
    float4 w = *(const float4*)(W + (size_t)rr * C + c * 4);
    uint32_t h0, l0, h1, l1;
    split2(w.x, w.y, h0, l0);
    split2(w.z, w.w, h1, l1);
    *(uint2*)&g_wh[(size_t)r * C + c * 4] = make_uint2(h0, h1);
    *(uint2*)&g_wl[(size_t)r * C + c * 4] = make_uint2(l0, l1);
}

// ===========================================================================
// Projection via mma.sync bf16x3, all inputs pre-split bf16.
// BM=64, N=192 (all 3 heads) per CTA -> grid 128.  K-chunks of 32, 32 iters.
// Double-buffered SMEM, cp.async wait_group(1) for load/compute overlap.
// 8 warps: warp tile M16 x N96 (wid&3 -> m-row, wid>>2 -> n-half).
// SMEM rows padded to 80B -> conflict-free ldmatrix.
// ===========================================================================
#define POFF_AH 0
#define POFF_AL 5120
#define POFF_BH 10240
#define POFF_BL 25600
#define PBUF    40960
#define PROJ_SMEM (2 * PBUF)
#define NIT 32

__global__ __launch_bounds__(256) void proj_mma_kernel()
{
    extern __shared__ char sm[];
    const uint32_t sb = smem_to_u32(sm);
    const int tid  = threadIdx.x;
    const int wid  = tid >> 5;
    const int lane = tid & 31;
    const int mblk = blockIdx.x * 64;

    // loader mappings
    const int arow = tid >> 2;        // 0..63
    const int ac   = tid & 3;         // 16B chunk (of 64B row)

    auto issue = [&](int it) {
        const int k0 = it * 32;
        const uint32_t bo = sb + (it & 1) * PBUF;
        cp16(bo + POFF_AH + arow * 80 + ac * 16, g_xh + (size_t)(mblk + arow) * C + k0 + ac * 8);
        cp16(bo + POFF_AL + arow * 80 + ac * 16, g_xl + (size_t)(mblk + arow) * C + k0 + ac * 8);
        #pragma unroll
        for (int i = 0; i < 3; i++) {
            int idx = i * 256 + tid;
            int r = idx >> 2;         // 0..191
            int c = idx & 3;
            cp16(bo + POFF_BH + r * 80 + c * 16, g_wh + (size_t)r * C + k0 + c * 8);
            cp16(bo + POFF_BL + r * 80 + c * 16, g_wl + (size_t)r * C + k0 + c * 8);
        }
        cp_commit();
    };

    float acc[12][4] = {};

    const int l7    = lane & 7;
    const int lb3   = (lane >> 3) & 1;
    const int lb4   = (lane >> 4) & 1;
    const int mrow  = (wid & 3) * 16;
    const int nbase = (wid >> 2) * 96;

    issue(0);

    for (int it = 0; it < NIT; it++) {
        const int p = it & 1;
        if (it + 1 < NIT) { issue(it + 1); cp_wait<1>(); }
        else              { cp_wait<0>(); }
        __syncthreads();

        const uint32_t bo = sb + p * PBUF;
        #pragma unroll
        for (int ks = 0; ks < 2; ks++) {
            const uint32_t aoff = (uint32_t)(mrow + lb3 * 8 + l7) * 80 + ks * 32 + lb4 * 16;
            uint32_t ah[4], al[4];
            ldsm4(ah, bo + POFF_AH + aoff);
            ldsm4(al, bo + POFF_AL + aoff);

            #pragma unroll
            for (int t = 0; t < 6; t++) {
                const uint32_t boff = (uint32_t)(nbase + t * 16 + lb4 * 8 + l7) * 80
                                    + (ks * 16 + lb3 * 8) * 2;
                uint32_t bh[4], bl[4];
                ldsm4(bh, bo + POFF_BH + boff);
                ldsm4(bl, bo + POFF_BL + boff);
                #pragma unroll
                for (int s2 = 0; s2 < 2; s2++) {
                    const int nt = t * 2 + s2;
                    mma16816(acc[nt], ah, &bh[s2 * 2]);
                    mma16816(acc[nt], ah, &bl[s2 * 2]);
                    mma16816(acc[nt], al, &bh[s2 * 2]);
                }
            }
        }
        __syncthreads();   // buffer p reusable by issue(it+2)
    }

    // epilogue
    const int g   = lane >> 2;
    const int tig = lane & 3;
    const int m1  = mblk + mrow + g;
    #pragma unroll
    for (int nt = 0; nt < 12; nt++) {
        const int col = nbase + nt * 8 + tig * 2;
        const int j   = col >> 6;
        const int hc  = col & 63;
        float* outp = (j == 0) ? g_q : ((j == 1) ? g_k : g_v);
        *(float2*)(outp + (size_t)m1 * H + hc)       = make_float2(acc[nt][0], acc[nt][1]);
        *(float2*)(outp + (size_t)(m1 + 8) * H + hc) = make_float2(acc[nt][2], acc[nt][3]);
    }
}

// ===========================================================================
// Flash attention partial (fp32 CUDA cores) — unchanged (known-good)
// ===========================================================================
__global__ __launch_bounds__(256) void attn_kernel()
{
    __shared__ float Qs[64 * 32];
    __shared__ float KP[64 * 68];
    __shared__ float Vs[64 * 68];

    const int tid = threadIdx.x;
    const int tm  = tid >> 4;
    const int tn  = tid & 15;
    const int m0  = tm * 2;
    const int c0  = tn * 4;
    const int b   = blockIdx.y;
    const int qt  = (T / 32 - 1) - blockIdx.x;
    const int sp  = blockIdx.z;
    const int q0  = qt * 32;

    const int kt_last = (q0 + 31) >> 6;
    const int ntiles  = kt_last + 1;
    const int mid     = (ntiles + 1) >> 1;
    const int kt_beg  = (sp == 0) ? 0   : mid;
    const int kt_end  = (sp == 0) ? mid : ntiles;

    const int r_base = b * T + q0;

    if (kt_beg >= kt_end) {
        #pragma unroll
        for (int i = 0; i < 2; i++) {
            *(float4*)&g_opart[sp][(size_t)(r_base + m0 + i) * H + c0] =
                make_float4(0.f, 0.f, 0.f, 0.f);
            if (tn == 0) {
                g_m[sp][r_base + m0 + i] = -1e30f;
                g_l[sp][r_base + m0 + i] = 0.f;
            }
        }
        return;
    }

    const float* qg = g_q + (size_t)b * T * H;
    const float* kg = g_k + (size_t)b * T * H;
    const float* vg = g_v + (size_t)b * T * H;

    #pragma unroll
    for (int i = 0; i < 2; i++) {
        int idx = i * 256 + tid;
        int m  = idx >> 4;
        int hq = idx & 15;
        float4 a = *(const float4*)(qg + (size_t)(q0 + m) * H + hq * 4);
        Qs[(hq * 4 + 0) * 32 + m] = a.x * 0.125f;
        Qs[(hq * 4 + 1) * 32 + m] = a.y * 0.125f;
        Qs[(hq * 4 + 2) * 32 + m] = a.z * 0.125f;
        Qs[(hq * 4 + 3) * 32 + m] = a.w * 0.125f;
    }

    float o[2][4]  = {};
    float run_m[2] = {-1e30f, -1e30f};
    float run_l[2] = {0.f, 0.f};

    for (int kt = kt_beg; kt < kt_end; kt++) {
        const int k0 = kt * 64;
        __syncthreads();

        #pragma unroll
        for (int i = 0; i < 4; i++) {
            int idx = i * 256 + tid;
            int n  = idx >> 4;
            int hq = idx & 15;
            float4 ka = *(const float4*)(kg + (size_t)(k0 + n) * H + hq * 4);
            KP[(hq * 4 + 0) * 68 + n] = ka.x;
            KP[(hq * 4 + 1) * 68 + n] = ka.y;
            KP[(hq * 4 + 2) * 68 + n] = ka.z;
            KP[(hq * 4 + 3) * 68 + n] = ka.w;
            float4 va = *(const float4*)(vg + (size_t)(k0 + n) * H + hq * 4);
            *(float4*)&Vs[n * 68 + hq * 4] = va;
        }
        __syncthreads();

        float s[2][4] = {};
        #pragma unroll
        for (int h = 0; h < 64; h++) {
            float2 a  = *(const float2*)&Qs[h * 32 + m0];
            float4 bk = *(const float4*)&KP[h * 68 + c0];
            s[0][0] += a.x * bk.x; s[0][1] += a.x * bk.y; s[0][2] += a.x * bk.z; s[0][3] += a.x * bk.w;
            s[1][0] += a.y * bk.x; s[1][1] += a.y * bk.y; s[1][2] += a.y * bk.z; s[1][3] += a.y * bk.w;
        }

        if (kt == kt_last) {
            #pragma unroll
            for (int i = 0; i < 2; i++)
                #pragma unroll
                for (int jj = 0; jj < 4; jj++)
                    if (k0 + c0 + jj > q0 + m0 + i) s[i][jj] = -1e30f;
        }

        #pragma unroll
        for (int i = 0; i < 2; i++) {
            float pm = fmaxf(fmaxf(s[i][0], s[i][1]), fmaxf(s[i][2], s[i][3]));
            pm = fmaxf(pm, __shfl_xor_sync(0xffffffffu, pm, 1));
            pm = fmaxf(pm, __shfl_xor_sync(0xffffffffu, pm, 2));
            pm = fmaxf(pm, __shfl_xor_sync(0xffffffffu, pm, 4));
            pm = fmaxf(pm, __shfl_xor_sync(0xffffffffu, pm, 8));
            float nm    = fmaxf(run_m[i], pm);
            float alpha = __expf(run_m[i] - nm);
            float rs = 0.f;
            #pragma unroll
            for (int jj = 0; jj < 4; jj++) {
                s[i][jj] = __expf(s[i][jj] - nm);
                rs += s[i][jj];
            }
            rs += __shfl_xor_sync(0xffffffffu, rs, 1);
            rs += __shfl_xor_sync(0xffffffffu, rs, 2);
            rs += __shfl_xor_sync(0xffffffffu, rs, 4);
            rs += __shfl_xor_sync(0xffffffffu, rs, 8);
            run_l[i] = run_l[i] * alpha + rs;
            run_m[i] = nm;
            #pragma unroll
            for (int jj = 0; jj < 4; jj++) o[i][jj] *= alpha;
        }

        __syncthreads();

        #pragma unroll
        for (int i = 0; i < 2; i++)
            #pragma unroll
            for (int jj = 0; jj < 4; jj++)
                KP[(c0 + jj) * 66 + m0 + i] = s[i][jj];
        __syncthreads();

        #pragma unroll
        for (int n = 0; n < 64; n++) {
            float2 p  = *(const float2*)&KP[n * 66 + m0];
            float4 vv = *(const float4*)&Vs[n * 68 + c0];
            o[0][0] += p.x * vv.x; o[0][1] += p.x * vv.y; o[0][2] += p.x * vv.z; o[0][3] += p.x * vv.w;
            o[1][0] += p.y * vv.x; o[1][1] += p.y * vv.y; o[1][2] += p.y * vv.z; o[1][3] += p.y * vv.w;
        }
    }

    #pragma unroll
    for (int i = 0; i < 2; i++) {
        *(float4*)&g_opart[sp][(size_t)(r_base + m0 + i) * H + c0] =
            make_float4(o[i][0], o[i][1], o[i][2], o[i][3]);
        if (tn == 0) {
            g_m[sp][r_base + m0 + i] = run_m[i];
            g_l[sp][r_base + m0 + i] = run_l[i];
        }
    }
}

// ===========================================================================
// Combine partials
// ===========================================================================
__global__ __launch_bounds__(256) void combine_kernel(float* __restrict__ out)
{
    int idx = blockIdx.x * 256 + threadIdx.x;
    int row = idx >> 4;
    int c4  = (idx & 15) * 4;

    float m1 = g_m[0][row], m2 = g_m[1][row];
    float l1 = g_l[0][row], l2 = g_l[1][row];
    float M  = fmaxf(m1, m2);
    float w1 = __expf(m1 - M);
    float w2 = __expf(m2 - M);
    float inv = 1.0f / (w1 * l1 + w2 * l2);

    float4 o1 = *(const float4*)&g_opart[0][(size_t)row * H + c4];
    float4 o2 = *(const float4*)&g_opart[1][(size_t)row * H + c4];
    float4 r;
    r.x = (w1 * o1.x + w2 * o2.x) * inv;
    r.y = (w1 * o1.y + w2 * o2.y) * inv;
    r.z = (w1 * o1.z + w2 * o2.z) * inv;
    r.w = (w1 * o1.w + w2 * o2.w) * inv;
    *(float4*)&out[(size_t)row * H + c4] = r;
}

// ===========================================================================
extern "C" void kernel_launch(void* const* d_in, const int* in_sizes, int n_in,
                              void* d_out, int out_size)
{
    const float* x  = (const float*)d_in[0];
    const float* Wq = (const float*)d_in[1];
    const float* Wk = (const float*)d_in[2];
    const float* Wv = (const float*)d_in[3];
    float* out = (float*)d_out;

    cudaFuncSetAttribute(proj_mma_kernel,
                         cudaFuncAttributeMaxDynamicSharedMemorySize, PROJ_SMEM);

    xconv_kernel<<<(M_TOTAL * C / 4) / 256, 256>>>(x);
    wconv_kernel<<<192, 256>>>(Wq, Wk, Wv);
    proj_mma_kernel<<<M_TOTAL / 64, 256, PROJ_SMEM>>>();
    attn_kernel<<<dim3(T / 32, BATCH, NSPLIT), 256>>>();
    combine_kernel<<<(M_TOTAL * (H / 4)) / 256, 256>>>(out);
}

// round 6
// speedup vs baseline: 3.2703x; 3.2344x over previous
#include <cuda_runtime.h>
#include <cuda_bf16.h>
#include <cstdint>

#define BATCH 4
#define T 2048
#define C 1024
#define H 64
#define M_TOTAL (BATCH * T)   // 8192
#define NSPLIT 2

// Scratch (allocation-free rule: __device__ globals)
__device__ float g_opart[NSPLIT][BATCH * T * H];
__device__ float g_m[NSPLIT][BATCH * T];
__device__ float g_l[NSPLIT][BATCH * T];
__device__ __nv_bfloat16 g_xh[M_TOTAL * C];    // x bf16 hi
__device__ __nv_bfloat16 g_xl[M_TOTAL * C];    // x bf16 lo
__device__ __nv_bfloat16 g_wh[192 * C];        // [Wq;Wk;Wv] bf16 hi
__device__ __nv_bfloat16 g_wl[192 * C];        // bf16 lo
__device__ __nv_bfloat16 g_qh[M_TOTAL * H];    // q (scale folded) hi/lo
__device__ __nv_bfloat16 g_ql[M_TOTAL * H];
__device__ __nv_bfloat16 g_kh[M_TOTAL * H];
__device__ __nv_bfloat16 g_kl[M_TOTAL * H];
__device__ __nv_bfloat16 g_vth[H * M_TOTAL];   // V transposed [h][m]
__device__ __nv_bfloat16 g_vtl[H * M_TOTAL];

// ===========================================================================
// Helpers (portable sm_80+ tensor path)
// ===========================================================================
__device__ __forceinline__ uint32_t smem_to_u32(const void* p) {
    uint32_t a;
    asm("{ .reg .u64 t; cvta.to.shared.u64 t, %1; cvt.u32.u64 %0, t; }" : "=r"(a) : "l"(p));
    return a;
}
__device__ __forceinline__ void ldsm4(uint32_t* r, uint32_t addr) {
    asm volatile("ldmatrix.sync.aligned.m8n8.x4.shared.b16 {%0,%1,%2,%3}, [%4];"
                 : "=r"(r[0]), "=r"(r[1]), "=r"(r[2]), "=r"(r[3]) : "r"(addr));
}
__device__ __forceinline__ void mma16816(float* d, const uint32_t* a, const uint32_t* b) {
    asm volatile(
        "mma.sync.aligned.m16n8k16.row.col.f32.bf16.bf16.f32 "
        "{%0,%1,%2,%3}, {%4,%5,%6,%7}, {%8,%9}, {%0,%1,%2,%3};"
        : "+f"(d[0]), "+f"(d[1]), "+f"(d[2]), "+f"(d[3])
        : "r"(a[0]), "r"(a[1]), "r"(a[2]), "r"(a[3]), "r"(b[0]), "r"(b[1]));
}
__device__ __forceinline__ void cp16(uint32_t smem_addr, const void* gptr) {
    asm volatile("cp.async.cg.shared.global [%0], [%1], 16;" :: "r"(smem_addr), "l"(gptr));
}
__device__ __forceinline__ void cp_commit() { asm volatile("cp.async.commit_group;" ::: "memory"); }
template <int N>
__device__ __forceinline__ void cp_wait() {
    asm volatile("cp.async.wait_group %0;" :: "n"(N) : "memory");
}

__device__ __forceinline__ void split2(float a, float b, uint32_t& hi, uint32_t& lo) {
    __nv_bfloat16 ha = __float2bfloat16_rn(a);
    __nv_bfloat16 hb = __float2bfloat16_rn(b);
    float ra = a - __bfloat162float(ha);
    float rb = b - __bfloat162float(hb);
    __nv_bfloat16 la = __float2bfloat16_rn(ra);
    __nv_bfloat16 lb = __float2bfloat16_rn(rb);
    hi = (uint32_t)__bfloat16_as_ushort(ha) | ((uint32_t)__bfloat16_as_ushort(hb) << 16);
    lo = (uint32_t)__bfloat16_as_ushort(la) | ((uint32_t)__bfloat16_as_ushort(lb) << 16);
}

// ===========================================================================
// x -> bf16 hi/lo  (memory-bound, once)
// ===========================================================================
__global__ __launch_bounds__(256) void xconv_kernel(const float* __restrict__ x)
{
    size_t idx = (size_t)blockIdx.x * 256 + threadIdx.x;
    float4 v = *(const float4*)(x + idx * 4);
    uint32_t h0, l0, h1, l1;
    split2(v.x, v.y, h0, l0);
    split2(v.z, v.w, h1, l1);
    *(uint2*)&g_xh[idx * 4] = make_uint2(h0, h1);
    *(uint2*)&g_xl[idx * 4] = make_uint2(l0, l1);
}

// ===========================================================================
// W -> bf16 hi/lo (tiny)
// ===========================================================================
__global__ __launch_bounds__(256) void wconv_kernel(
    const float* __restrict__ Wq, const float* __restrict__ Wk, const float* __restrict__ Wv)
{
    int idx = blockIdx.x * 256 + threadIdx.x;
    int r = idx >> 8;
    int c = idx & 255;
    const float* W = (r < 64) ? Wq : ((r < 128) ? Wk : Wv);
    int rr = r & 63;
    float4 w = *(const float4*)(W + (size_t)rr * C + c * 4);
    uint32_t h0, l0, h1, l1;
    split2(w.x, w.y, h0, l0);
    split2(w.z, w.w, h1, l1);
    *(uint2*)&g_wh[(size_t)r * C + c * 4] = make_uint2(h0, h1);
    *(uint2*)&g_wl[(size_t)r * C + c * 4] = make_uint2(l0, l1);
}

// ===========================================================================
// Projection via mma.sync bf16x3.  BM=64, N=192 per CTA, grid 128.
// Epilogue emits bf16 hi/lo: q (x0.125), k, and TRANSPOSED v.
// ===========================================================================
#define POFF_AH 0
#define POFF_AL 5120
#define POFF_BH 10240
#define POFF_BL 25600
#define PBUF    40960
#define PROJ_SMEM (2 * PBUF)
#define NIT 32

__global__ __launch_bounds__(256) void proj_mma_kernel()
{
    extern __shared__ char sm[];
    const uint32_t sb = smem_to_u32(sm);
    const int tid  = threadIdx.x;
    const int wid  = tid >> 5;
    const int lane = tid & 31;
    const int mblk = blockIdx.x * 64;

    const int arow = tid >> 2;
    const int ac   = tid & 3;

    auto issue = [&](int it) {
        const int k0 = it * 32;
        const uint32_t bo = sb + (it & 1) * PBUF;
        cp16(bo + POFF_AH + arow * 80 + ac * 16, g_xh + (size_t)(mblk + arow) * C + k0 + ac * 8);
        cp16(bo + POFF_AL + arow * 80 + ac * 16, g_xl + (size_t)(mblk + arow) * C + k0 + ac * 8);
        #pragma unroll
        for (int i = 0; i < 3; i++) {
            int idx = i * 256 + tid;
            int r = idx >> 2;
            int c = idx & 3;
            cp16(bo + POFF_BH + r * 80 + c * 16, g_wh + (size_t)r * C + k0 + c * 8);
            cp16(bo + POFF_BL + r * 80 + c * 16, g_wl + (size_t)r * C + k0 + c * 8);
        }
        cp_commit();
    };

    float acc[12][4] = {};

    const int l7    = lane & 7;
    const int lb3   = (lane >> 3) & 1;
    const int lb4   = (lane >> 4) & 1;
    const int mrow  = (wid & 3) * 16;
    const int nbase = (wid >> 2) * 96;

    issue(0);

    for (int it = 0; it < NIT; it++) {
        const int p = it & 1;
        if (it + 1 < NIT) { issue(it + 1); cp_wait<1>(); }
        else              { cp_wait<0>(); }
        __syncthreads();

        const uint32_t bo = sb + p * PBUF;
        #pragma unroll
        for (int ks = 0; ks < 2; ks++) {
            const uint32_t aoff = (uint32_t)(mrow + lb3 * 8 + l7) * 80 + ks * 32 + lb4 * 16;
            uint32_t ah[4], al[4];
            ldsm4(ah, bo + POFF_AH + aoff);
            ldsm4(al, bo + POFF_AL + aoff);

            #pragma unroll
            for (int t = 0; t < 6; t++) {
                const uint32_t boff = (uint32_t)(nbase + t * 16 + lb4 * 8 + l7) * 80
                                    + (ks * 16 + lb3 * 8) * 2;
                uint32_t bh[4], bl[4];
                ldsm4(bh, bo + POFF_BH + boff);
                ldsm4(bl, bo + POFF_BL + boff);
                #pragma unroll
                for (int s2 = 0; s2 < 2; s2++) {
                    const int nt = t * 2 + s2;
                    mma16816(acc[nt], ah, &bh[s2 * 2]);
                    mma16816(acc[nt], ah, &bl[s2 * 2]);
                    mma16816(acc[nt], al, &bh[s2 * 2]);
                }
            }
        }
        __syncthreads();
    }

    // epilogue -> bf16 hi/lo globals
    const int g   = lane >> 2;
    const int tig = lane & 3;
    const int m1  = mblk + mrow + g;
    #pragma unroll
    for (int nt = 0; nt < 12; nt++) {
        const int col = nbase + nt * 8 + tig * 2;
        const int j   = col >> 6;
        const int hc  = col & 63;
        if (j == 0) {
            uint32_t h0, l0;
            split2(acc[nt][0] * 0.125f, acc[nt][1] * 0.125f, h0, l0);
            *(uint32_t*)&g_qh[(size_t)m1 * H + hc] = h0;
            *(uint32_t*)&g_ql[(size_t)m1 * H + hc] = l0;
            split2(acc[nt][2] * 0.125f, acc[nt][3] * 0.125f, h0, l0);
            *(uint32_t*)&g_qh[(size_t)(m1 + 8) * H + hc] = h0;
            *(uint32_t*)&g_ql[(size_t)(m1 + 8) * H + hc] = l0;
        } else if (j == 1) {
            uint32_t h0, l0;
            split2(acc[nt][0], acc[nt][1], h0, l0);
            *(uint32_t*)&g_kh[(size_t)m1 * H + hc] = h0;
            *(uint32_t*)&g_kl[(size_t)m1 * H + hc] = l0;
            split2(acc[nt][2], acc[nt][3], h0, l0);
            *(uint32_t*)&g_kh[(size_t)(m1 + 8) * H + hc] = h0;
            *(uint32_t*)&g_kl[(size_t)(m1 + 8) * H + hc] = l0;
        } else {
            #pragma unroll
            for (int k = 0; k < 4; k++) {
                int r  = m1 + (k >> 1) * 8;
                int cc = hc + (k & 1);
                float v = acc[nt][k];
                __nv_bfloat16 hi = __float2bfloat16_rn(v);
                __nv_bfloat16 lo = __float2bfloat16_rn(v - __bfloat162float(hi));
                g_vth[(size_t)cc * M_TOTAL + r] = hi;
                g_vtl[(size_t)cc * M_TOTAL + r] = lo;
            }
        }
    }
}

// ===========================================================================
// Flash attention on mma.sync, bf16x3.  BM=64, BN=64, 8 warps.
// Warp (wm = wid&3, wn = wid>>2): rows 16*wm, col-half 32*wn.
// Split-KV over blockIdx.z, heavy-first q-tile order.
// ===========================================================================
#define STR 144                  // SMEM row stride bytes (64 bf16 + 16B pad)
#define A_QH 0
#define A_QL 9216
#define A_KH 18432
#define A_KL 27648
#define A_VH 36864
#define A_VL 46080
#define A_PH 55296
#define A_PL 64512
#define A_MAX 73728              // float[2][64]
#define A_SUM 74240              // float[2][64]
#define ATTN_SMEM 74752

__global__ __launch_bounds__(256) void attn_mma_kernel()
{
    extern __shared__ char sm[];
    const uint32_t sb = smem_to_u32(sm);
    const int tid  = threadIdx.x;
    const int wid  = tid >> 5;
    const int lane = tid & 31;
    const int wm = wid & 3, wn = wid >> 2;
    const int g = lane >> 2, tig = lane & 3;
    const int l7 = lane & 7, lb3 = (lane >> 3) & 1, lb4 = (lane >> 4) & 1;

    const int b  = blockIdx.y;
    const int sp = blockIdx.z;
    const int qt = (T / 64 - 1) - blockIdx.x;   // heavy-first
    const int q0 = qt * 64;
    const int bT = b * T;

    const int ntiles = qt + 1;
    const int mid    = (ntiles + 1) >> 1;
    const int kt_beg = sp ? mid : 0;
    const int kt_end = sp ? ntiles : mid;

    const int rr0  = 16 * wm + g;
    const int orow = bT + q0 + rr0;

    if (kt_beg >= kt_end) {   // empty split: neutral partials
        #pragma unroll
        for (int nt = 0; nt < 4; nt++) {
            int c = 32 * wn + nt * 8 + tig * 2;
            *(float2*)&g_opart[sp][(size_t)orow * H + c]       = make_float2(0.f, 0.f);
            *(float2*)&g_opart[sp][(size_t)(orow + 8) * H + c] = make_float2(0.f, 0.f);
        }
        if (wn == 0 && tig == 0) {
            g_m[sp][orow] = -1e30f; g_m[sp][orow + 8] = -1e30f;
            g_l[sp][orow] = 0.f;    g_l[sp][orow + 8] = 0.f;
        }
        return;
    }

    auto loadK = [&](int kt) {
        int k0 = kt * 64;
        #pragma unroll
        for (int i = 0; i < 2; i++) {
            int idx = i * 256 + tid, r = idx >> 3, c = idx & 7;
            cp16(sb + A_KH + r * STR + c * 16, g_kh + (size_t)(bT + k0 + r) * H + c * 8);
            cp16(sb + A_KL + r * STR + c * 16, g_kl + (size_t)(bT + k0 + r) * H + c * 8);
        }
        cp_commit();
    };
    auto loadV = [&](int kt) {
        int k0 = kt * 64;
        #pragma unroll
        for (int i = 0; i < 2; i++) {
            int idx = i * 256 + tid, r = idx >> 3, c = idx & 7;   // r = h row
            cp16(sb + A_VH + r * STR + c * 16, g_vth + (size_t)r * M_TOTAL + bT + k0 + c * 8);
            cp16(sb + A_VL + r * STR + c * 16, g_vtl + (size_t)r * M_TOTAL + bT + k0 + c * 8);
        }
        cp_commit();
    };

    // prologue: {Q + K(kt_beg)} group, then {V(kt_beg)} group
    #pragma unroll
    for (int i = 0; i < 2; i++) {
        int idx = i * 256 + tid, r = idx >> 3, c = idx & 7;
        cp16(sb + A_QH + r * STR + c * 16, g_qh + (size_t)(bT + q0 + r) * H + c * 8);
        cp16(sb + A_QL + r * STR + c * 16, g_ql + (size_t)(bT + q0 + r) * H + c * 8);
    }
    loadK(kt_beg);
    loadV(kt_beg);

    float O[4][4] = {};
    float run_m[2] = {-1e30f, -1e30f};
    float run_l[2] = {0.f, 0.f};
    float* smax = (float*)(sm + A_MAX);
    float* ssum = (float*)(sm + A_SUM);

    for (int kt = kt_beg; kt < kt_end; kt++) {
        cp_wait<1>();            // Q+K of this tile arrived
        __syncthreads();         // S0

        // ---- S = Q K^T (bf16x3)
        float S[4][4] = {};
        #pragma unroll
        for (int ks = 0; ks < 4; ks++) {
            uint32_t ah[4], al[4];
            uint32_t aoff = (uint32_t)(16 * wm + lb3 * 8 + l7) * STR + ks * 32 + lb4 * 16;
            ldsm4(ah, sb + A_QH + aoff);
            ldsm4(al, sb + A_QL + aoff);
            #pragma unroll
            for (int t = 0; t < 2; t++) {
                uint32_t bh[4], bl[4];
                uint32_t boff = (uint32_t)(32 * wn + t * 16 + lb4 * 8 + l7) * STR + ks * 32 + lb3 * 16;
                ldsm4(bh, sb + A_KH + boff);
                ldsm4(bl, sb + A_KL + boff);
                #pragma unroll
                for (int s2 = 0; s2 < 2; s2++) {
                    const int nt = t * 2 + s2;
                    mma16816(S[nt], ah, &bh[s2 * 2]);
                    mma16816(S[nt], ah, &bl[s2 * 2]);
                    mma16816(S[nt], al, &bh[s2 * 2]);
                }
            }
        }

        const int k0 = kt * 64;
        if (kt == qt) {   // diagonal mask
            #pragma unroll
            for (int nt = 0; nt < 4; nt++)
                #pragma unroll
                for (int k = 0; k < 4; k++) {
                    int row = q0 + rr0 + (k >> 1) * 8;
                    int col = k0 + 32 * wn + nt * 8 + tig * 2 + (k & 1);
                    if (col > row) S[nt][k] = -1e30f;
                }
        }

        // ---- row max (in-warp + cross-warp via SMEM)
        float pm0 = -1e30f, pm1 = -1e30f;
        #pragma unroll
        for (int nt = 0; nt < 4; nt++) {
            pm0 = fmaxf(pm0, fmaxf(S[nt][0], S[nt][1]));
            pm1 = fmaxf(pm1, fmaxf(S[nt][2], S[nt][3]));
        }
        pm0 = fmaxf(pm0, __shfl_xor_sync(~0u, pm0, 1));
        pm0 = fmaxf(pm0, __shfl_xor_sync(~0u, pm0, 2));
        pm1 = fmaxf(pm1, __shfl_xor_sync(~0u, pm1, 1));
        pm1 = fmaxf(pm1, __shfl_xor_sync(~0u, pm1, 2));
        if (tig == 0) { smax[wn * 64 + rr0] = pm0; smax[wn * 64 + rr0 + 8] = pm1; }
        __syncthreads();         // S1 (also: all QK^T reads of K done)

        if (kt + 1 < kt_end) loadK(kt + 1);   // overlap next-K with softmax+PV

        float nm0 = fmaxf(run_m[0], fmaxf(smax[rr0],     smax[64 + rr0]));
        float nm1 = fmaxf(run_m[1], fmaxf(smax[rr0 + 8], smax[64 + rr0 + 8]));
        float al0 = __expf(run_m[0] - nm0);
        float al1 = __expf(run_m[1] - nm1);

        float rs0 = 0.f, rs1 = 0.f;
        #pragma unroll
        for (int nt = 0; nt < 4; nt++) {
            float p0 = __expf(S[nt][0] - nm0), p1 = __expf(S[nt][1] - nm0);
            float p2 = __expf(S[nt][2] - nm1), p3 = __expf(S[nt][3] - nm1);
            rs0 += p0 + p1; rs1 += p2 + p3;
            uint32_t h0, l0, h1, l1;
            split2(p0, p1, h0, l0);
            split2(p2, p3, h1, l1);
            uint32_t cb = (uint32_t)(32 * wn + nt * 8 + tig * 2) * 2;
            *(uint32_t*)(sm + A_PH + rr0 * STR + cb) = h0;
            *(uint32_t*)(sm + A_PL + rr0 * STR + cb) = l0;
            *(uint32_t*)(sm + A_PH + (rr0 + 8) * STR + cb) = h1;
            *(uint32_t*)(sm + A_PL + (rr0 + 8) * STR + cb) = l1;
        }
        rs0 += __shfl_xor_sync(~0u, rs0, 1); rs0 += __shfl_xor_sync(~0u, rs0, 2);
        rs1 += __shfl_xor_sync(~0u, rs1, 1); rs1 += __shfl_xor_sync(~0u, rs1, 2);
        if (tig == 0) { ssum[wn * 64 + rr0] = rs0; ssum[wn * 64 + rr0 + 8] = rs1; }

        if (kt + 1 < kt_end) cp_wait<1>();    // V of this tile arrived (next-K in flight)
        else                 cp_wait<0>();
        __syncthreads();         // S2 (P, sums, V visible)

        run_l[0] = run_l[0] * al0 + ssum[rr0]     + ssum[64 + rr0];
        run_l[1] = run_l[1] * al1 + ssum[rr0 + 8] + ssum[64 + rr0 + 8];
        run_m[0] = nm0; run_m[1] = nm1;
        #pragma unroll
        for (int nt = 0; nt < 4; nt++) {
            O[nt][0] *= al0; O[nt][1] *= al0; O[nt][2] *= al1; O[nt][3] *= al1;
        }

        // ---- O += P V (bf16x3)
        #pragma unroll
        for (int kk = 0; kk < 4; kk++) {
            uint32_t ph[4], pl[4];
            uint32_t aoff = (uint32_t)(16 * wm + lb3 * 8 + l7) * STR + kk * 32 + lb4 * 16;
            ldsm4(ph, sb + A_PH + aoff);
            ldsm4(pl, sb + A_PL + aoff);
            #pragma unroll
            for (int t = 0; t < 2; t++) {
                uint32_t vh[4], vl[4];
                uint32_t boff = (uint32_t)(32 * wn + t * 16 + lb4 * 8 + l7) * STR + kk * 32 + lb3 * 16;
                ldsm4(vh, sb + A_VH + boff);
                ldsm4(vl, sb + A_VL + boff);
                #pragma unroll
                for (int s2 = 0; s2 < 2; s2++) {
                    const int nt = t * 2 + s2;
                    mma16816(O[nt], ph, &vh[s2 * 2]);
                    mma16816(O[nt], ph, &vl[s2 * 2]);
                    mma16816(O[nt], pl, &vh[s2 * 2]);
                }
            }
        }
        __syncthreads();         // S3 (V reads done -> buffer reusable)
        if (kt + 1 < kt_end) loadV(kt + 1);
    }

    // epilogue: unnormalized O + (m, l)
    #pragma unroll
    for (int nt = 0; nt < 4; nt++) {
        int c = 32 * wn + nt * 8 + tig * 2;
        *(float2*)&g_opart[sp][(size_t)orow * H + c]       = make_float2(O[nt][0], O[nt][1]);
        *(float2*)&g_opart[sp][(size_t)(orow + 8) * H + c] = make_float2(O[nt][2], O[nt][3]);
    }
    if (wn == 0 && tig == 0) {
        g_m[sp][orow] = run_m[0]; g_m[sp][orow + 8] = run_m[1];
        g_l[sp][orow] = run_l[0]; g_l[sp][orow + 8] = run_l[1];
    }
}

// ===========================================================================
// Combine partials
// ===========================================================================
__global__ __launch_bounds__(256) void combine_kernel(float* __restrict__ out)
{
    int idx = blockIdx.x * 256 + threadIdx.x;
    int row = idx >> 4;
    int c4  = (idx & 15) * 4;

    float m1 = g_m[0][row], m2 = g_m[1][row];
    float l1 = g_l[0][row], l2 = g_l[1][row];
    float M  = fmaxf(m1, m2);
    float w1 = __expf(m1 - M);
    float w2 = __expf(m2 - M);
    float inv = 1.0f / (w1 * l1 + w2 * l2);

    float4 o1 = *(const float4*)&g_opart[0][(size_t)row * H + c4];
    float4 o2 = *(const float4*)&g_opart[1][(size_t)row * H + c4];
    float4 r;
    r.x = (w1 * o1.x + w2 * o2.x) * inv;
    r.y = (w1 * o1.y + w2 * o2.y) * inv;
    r.z = (w1 * o1.z + w2 * o2.z) * inv;
    r.w = (w1 * o1.w + w2 * o2.w) * inv;
    *(float4*)&out[(size_t)row * H + c4] = r;
}

// ===========================================================================
extern "C" void kernel_launch(void* const* d_in, const int* in_sizes, int n_in,
                              void* d_out, int out_size)
{
    const float* x  = (const float*)d_in[0];
    const float* Wq = (const float*)d_in[1];
    const float* Wk = (const float*)d_in[2];
    const float* Wv = (const float*)d_in[3];
    float* out = (float*)d_out;

    cudaFuncSetAttribute(proj_mma_kernel,
                         cudaFuncAttributeMaxDynamicSharedMemorySize, PROJ_SMEM);
    cudaFuncSetAttribute(attn_mma_kernel,
                         cudaFuncAttributeMaxDynamicSharedMemorySize, ATTN_SMEM);

    xconv_kernel<<<(M_TOTAL * C / 4) / 256, 256>>>(x);
    wconv_kernel<<<192, 256>>>(Wq, Wk, Wv);
    proj_mma_kernel<<<M_TOTAL / 64, 256, PROJ_SMEM>>>();
    attn_mma_kernel<<<dim3(T / 64, BATCH, NSPLIT), 256, ATTN_SMEM>>>();
    combine_kernel<<<(M_TOTAL * (H / 4)) / 256, 256>>>(out);
}

// round 7
// speedup vs baseline: 3.8629x; 1.1812x over previous
#include <cuda_runtime.h>
#include <cuda_bf16.h>
#include <cstdint>

#define BATCH 4
#define T 2048
#define C 1024
#define H 64
#define M_TOTAL (BATCH * T)   // 8192
#define NSPLIT 4

// Scratch (allocation-free rule: __device__ globals)
__device__ float g_opart[NSPLIT][BATCH * T * H];
__device__ float g_m[NSPLIT][BATCH * T];
__device__ float g_l[NSPLIT][BATCH * T];
__device__ __nv_bfloat16 g_xh[M_TOTAL * C];    // x bf16 hi
__device__ __nv_bfloat16 g_xl[M_TOTAL * C];    // x bf16 lo
__device__ __nv_bfloat16 g_wh[192 * C];        // [Wq;Wk;Wv] bf16 hi
__device__ __nv_bfloat16 g_wl[192 * C];        // bf16 lo
__device__ __nv_bfloat16 g_qh[M_TOTAL * H];    // q (scale folded) hi/lo
__device__ __nv_bfloat16 g_ql[M_TOTAL * H];
__device__ __nv_bfloat16 g_kh[M_TOTAL * H];
__device__ __nv_bfloat16 g_kl[M_TOTAL * H];
__device__ __nv_bfloat16 g_vth[H * M_TOTAL];   // V transposed [h][m]
__device__ __nv_bfloat16 g_vtl[H * M_TOTAL];

// ===========================================================================
// Helpers (portable sm_80+ tensor path)
// ===========================================================================
__device__ __forceinline__ uint32_t smem_to_u32(const void* p) {
    uint32_t a;
    asm("{ .reg .u64 t; cvta.to.shared.u64 t, %1; cvt.u32.u64 %0, t; }" : "=r"(a) : "l"(p));
    return a;
}
__device__ __forceinline__ void ldsm4(uint32_t* r, uint32_t addr) {
    asm volatile("ldmatrix.sync.aligned.m8n8.x4.shared.b16 {%0,%1,%2,%3}, [%4];"
                 : "=r"(r[0]), "=r"(r[1]), "=r"(r[2]), "=r"(r[3]) : "r"(addr));
}
__device__ __forceinline__ void mma16816(float* d, const uint32_t* a, const uint32_t* b) {
    asm volatile(
        "mma.sync.aligned.m16n8k16.row.col.f32.bf16.bf16.f32 "
        "{%0,%1,%2,%3}, {%4,%5,%6,%7}, {%8,%9}, {%0,%1,%2,%3};"
        : "+f"(d[0]), "+f"(d[1]), "+f"(d[2]), "+f"(d[3])
        : "r"(a[0]), "r"(a[1]), "r"(a[2]), "r"(a[3]), "r"(b[0]), "r"(b[1]));
}
__device__ __forceinline__ void cp16(uint32_t smem_addr, const void* gptr) {
    asm volatile("cp.async.cg.shared.global [%0], [%1], 16;" :: "r"(smem_addr), "l"(gptr));
}
__device__ __forceinline__ void cp_commit() { asm volatile("cp.async.commit_group;" ::: "memory"); }
template <int N>
__device__ __forceinline__ void cp_wait() {
    asm volatile("cp.async.wait_group %0;" :: "n"(N) : "memory");
}

__device__ __forceinline__ void split2(float a, float b, uint32_t& hi, uint32_t& lo) {
    __nv_bfloat16 ha = __float2bfloat16_rn(a);
    __nv_bfloat16 hb = __float2bfloat16_rn(b);
    float ra = a - __bfloat162float(ha);
    float rb = b - __bfloat162float(hb);
    __nv_bfloat16 la = __float2bfloat16_rn(ra);
    __nv_bfloat16 lb = __float2bfloat16_rn(rb);
    hi = (uint32_t)__bfloat16_as_ushort(ha) | ((uint32_t)__bfloat16_as_ushort(hb) << 16);
    lo = (uint32_t)__bfloat16_as_ushort(la) | ((uint32_t)__bfloat16_as_ushort(lb) << 16);
}

// ===========================================================================
// x -> bf16 hi/lo  (memory-bound, once)
// ===========================================================================
__global__ __launch_bounds__(256) void xconv_kernel(const float* __restrict__ x)
{
    size_t idx = (size_t)blockIdx.x * 256 + threadIdx.x;
    float4 v = *(const float4*)(x + idx * 4);
    uint32_t h0, l0, h1, l1;
    split2(v.x, v.y, h0, l0);
    split2(v.z, v.w, h1, l1);
    *(uint2*)&g_xh[idx * 4] = make_uint2(h0, h1);
    *(uint2*)&g_xl[idx * 4] = make_uint2(l0, l1);
}

// ===========================================================================
// W -> bf16 hi/lo (tiny)
// ===========================================================================
__global__ __launch_bounds__(256) void wconv_kernel(
    const float* __restrict__ Wq, const float* __restrict__ Wk, const float* __restrict__ Wv)
{
    int idx = blockIdx.x * 256 + threadIdx.x;
    int r = idx >> 8;
    int c = idx & 255;
    const float* W = (r < 64) ? Wq : ((r < 128) ? Wk : Wv);
    int rr = r & 63;
    float4 w = *(const float4*)(W + (size_t)rr * C + c * 4);
    uint32_t h0, l0, h1, l1;
    split2(w.x, w.y, h0, l0);
    split2(w.z, w.w, h1, l1);
    *(uint2*)&g_wh[(size_t)r * C + c * 4] = make_uint2(h0, h1);
    *(uint2*)&g_wl[(size_t)r * C + c * 4] = make_uint2(l0, l1);
}

// ===========================================================================
// Projection via mma.sync bf16x3.  BM=64, N=192 per CTA, grid 128.
// Epilogue emits bf16 hi/lo: q (x0.125), k, and TRANSPOSED v.
// ===========================================================================
#define POFF_AH 0
#define POFF_AL 5120
#define POFF_BH 10240
#define POFF_BL 25600
#define PBUF    40960
#define PROJ_SMEM (2 * PBUF)
#define NIT 32

__global__ __launch_bounds__(256) void proj_mma_kernel()
{
    extern __shared__ char sm[];
    const uint32_t sb = smem_to_u32(sm);
    const int tid  = threadIdx.x;
    const int wid  = tid >> 5;
    const int lane = tid & 31;
    const int mblk = blockIdx.x * 64;

    const int arow = tid >> 2;
    const int ac   = tid & 3;

    auto issue = [&](int it) {
        const int k0 = it * 32;
        const uint32_t bo = sb + (it & 1) * PBUF;
        cp16(bo + POFF_AH + arow * 80 + ac * 16, g_xh + (size_t)(mblk + arow) * C + k0 + ac * 8);
        cp16(bo + POFF_AL + arow * 80 + ac * 16, g_xl + (size_t)(mblk + arow) * C + k0 + ac * 8);
        #pragma unroll
        for (int i = 0; i < 3; i++) {
            int idx = i * 256 + tid;
            int r = idx >> 2;
            int c = idx & 3;
            cp16(bo + POFF_BH + r * 80 + c * 16, g_wh + (size_t)r * C + k0 + c * 8);
            cp16(bo + POFF_BL + r * 80 + c * 16, g_wl + (size_t)r * C + k0 + c * 8);
        }
        cp_commit();
    };

    float acc[12][4] = {};

    const int l7    = lane & 7;
    const int lb3   = (lane >> 3) & 1;
    const int lb4   = (lane >> 4) & 1;
    const int mrow  = (wid & 3) * 16;
    const int nbase = (wid >> 2) * 96;

    issue(0);

    for (int it = 0; it < NIT; it++) {
        const int p = it & 1;
        if (it + 1 < NIT) { issue(it + 1); cp_wait<1>(); }
        else              { cp_wait<0>(); }
        __syncthreads();

        const uint32_t bo = sb + p * PBUF;
        #pragma unroll
        for (int ks = 0; ks < 2; ks++) {
            const uint32_t aoff = (uint32_t)(mrow + lb3 * 8 + l7) * 80 + ks * 32 + lb4 * 16;
            uint32_t ah[4], al[4];
            ldsm4(ah, bo + POFF_AH + aoff);
            ldsm4(al, bo + POFF_AL + aoff);

            #pragma unroll
            for (int t = 0; t < 6; t++) {
                const uint32_t boff = (uint32_t)(nbase + t * 16 + lb4 * 8 + l7) * 80
                                    + (ks * 16 + lb3 * 8) * 2;
                uint32_t bh[4], bl[4];
                ldsm4(bh, bo + POFF_BH + boff);
                ldsm4(bl, bo + POFF_BL + boff);
                #pragma unroll
                for (int s2 = 0; s2 < 2; s2++) {
                    const int nt = t * 2 + s2;
                    mma16816(acc[nt], ah, &bh[s2 * 2]);
                    mma16816(acc[nt], ah, &bl[s2 * 2]);
                    mma16816(acc[nt], al, &bh[s2 * 2]);
                }
            }
        }
        __syncthreads();
    }

    // epilogue -> bf16 hi/lo globals
    const int g   = lane >> 2;
    const int tig = lane & 3;
    const int m1  = mblk + mrow + g;
    #pragma unroll
    for (int nt = 0; nt < 12; nt++) {
        const int col = nbase + nt * 8 + tig * 2;
        const int j   = col >> 6;
        const int hc  = col & 63;
        if (j == 0) {
            uint32_t h0, l0;
            split2(acc[nt][0] * 0.125f, acc[nt][1] * 0.125f, h0, l0);
            *(uint32_t*)&g_qh[(size_t)m1 * H + hc] = h0;
            *(uint32_t*)&g_ql[(size_t)m1 * H + hc] = l0;
            split2(acc[nt][2] * 0.125f, acc[nt][3] * 0.125f, h0, l0);
            *(uint32_t*)&g_qh[(size_t)(m1 + 8) * H + hc] = h0;
            *(uint32_t*)&g_ql[(size_t)(m1 + 8) * H + hc] = l0;
        } else if (j == 1) {
            uint32_t h0, l0;
            split2(acc[nt][0], acc[nt][1], h0, l0);
            *(uint32_t*)&g_kh[(size_t)m1 * H + hc] = h0;
            *(uint32_t*)&g_kl[(size_t)m1 * H + hc] = l0;
            split2(acc[nt][2], acc[nt][3], h0, l0);
            *(uint32_t*)&g_kh[(size_t)(m1 + 8) * H + hc] = h0;
            *(uint32_t*)&g_kl[(size_t)(m1 + 8) * H + hc] = l0;
        } else {
            #pragma unroll
            for (int k = 0; k < 4; k++) {
                int r  = m1 + (k >> 1) * 8;
                int cc = hc + (k & 1);
                float v = acc[nt][k];
                __nv_bfloat16 hi = __float2bfloat16_rn(v);
                __nv_bfloat16 lo = __float2bfloat16_rn(v - __bfloat162float(hi));
                g_vth[(size_t)cc * M_TOTAL + r] = hi;
                g_vtl[(size_t)cc * M_TOTAL + r] = lo;
            }
        }
    }
}

// ===========================================================================
// Flash attention on mma.sync, bf16x3.  BM=64, BN=64, 8 warps.
// Split-KV over blockIdx.z (NSPLIT=4), heavy-first q-tile order.
// ===========================================================================
#define STR 144                  // SMEM row stride bytes (64 bf16 + 16B pad)
#define A_QH 0
#define A_QL 9216
#define A_KH 18432
#define A_KL 27648
#define A_VH 36864
#define A_VL 46080
#define A_PH 55296
#define A_PL 64512
#define A_MAX 73728              // float[2][64]
#define A_SUM 74240              // float[2][64]
#define ATTN_SMEM 74752

__global__ __launch_bounds__(256) void attn_mma_kernel()
{
    extern __shared__ char sm[];
    const uint32_t sb = smem_to_u32(sm);
    const int tid  = threadIdx.x;
    const int wid  = tid >> 5;
    const int lane = tid & 31;
    const int wm = wid & 3, wn = wid >> 2;
    const int g = lane >> 2, tig = lane & 3;
    const int l7 = lane & 7, lb3 = (lane >> 3) & 1, lb4 = (lane >> 4) & 1;

    const int b  = blockIdx.y;
    const int sp = blockIdx.z;
    const int qt = (T / 64 - 1) - blockIdx.x;   // heavy-first
    const int q0 = qt * 64;
    const int bT = b * T;

    const int ntiles = qt + 1;
    const int kt_beg = (sp * ntiles) >> 2;
    const int kt_end = ((sp + 1) * ntiles) >> 2;

    const int rr0  = 16 * wm + g;
    const int orow = bT + q0 + rr0;

    if (kt_beg >= kt_end) {   // empty split: neutral partials
        #pragma unroll
        for (int nt = 0; nt < 4; nt++) {
            int c = 32 * wn + nt * 8 + tig * 2;
            *(float2*)&g_opart[sp][(size_t)orow * H + c]       = make_float2(0.f, 0.f);
            *(float2*)&g_opart[sp][(size_t)(orow + 8) * H + c] = make_float2(0.f, 0.f);
        }
        if (wn == 0 && tig == 0) {
            g_m[sp][orow] = -1e30f; g_m[sp][orow + 8] = -1e30f;
            g_l[sp][orow] = 0.f;    g_l[sp][orow + 8] = 0.f;
        }
        return;
    }

    auto loadK = [&](int kt) {
        int k0 = kt * 64;
        #pragma unroll
        for (int i = 0; i < 2; i++) {
            int idx = i * 256 + tid, r = idx >> 3, c = idx & 7;
            cp16(sb + A_KH + r * STR + c * 16, g_kh + (size_t)(bT + k0 + r) * H + c * 8);
            cp16(sb + A_KL + r * STR + c * 16, g_kl + (size_t)(bT + k0 + r) * H + c * 8);
        }
        cp_commit();
    };
    auto loadV = [&](int kt) {
        int k0 = kt * 64;
        #pragma unroll
        for (int i = 0; i < 2; i++) {
            int idx = i * 256 + tid, r = idx >> 3, c = idx & 7;   // r = h row
            cp16(sb + A_VH + r * STR + c * 16, g_vth + (size_t)r * M_TOTAL + bT + k0 + c * 8);
            cp16(sb + A_VL + r * STR + c * 16, g_vtl + (size_t)r * M_TOTAL + bT + k0 + c * 8);
        }
        cp_commit();
    };

    // prologue: {Q + K(kt_beg)} group, then {V(kt_beg)} group
    #pragma unroll
    for (int i = 0; i < 2; i++) {
        int idx = i * 256 + tid, r = idx >> 3, c = idx & 7;
        cp16(sb + A_QH + r * STR + c * 16, g_qh + (size_t)(bT + q0 + r) * H + c * 8);
        cp16(sb + A_QL + r * STR + c * 16, g_ql + (size_t)(bT + q0 + r) * H + c * 8);
    }
    loadK(kt_beg);
    loadV(kt_beg);

    float O[4][4] = {};
    float run_m[2] = {-1e30f, -1e30f};
    float run_l[2] = {0.f, 0.f};
    float* smax = (float*)(sm + A_MAX);
    float* ssum = (float*)(sm + A_SUM);

    for (int kt = kt_beg; kt < kt_end; kt++) {
        cp_wait<1>();            // Q+K of this tile arrived
        __syncthreads();         // S0

        // ---- S = Q K^T (bf16x3)
        float S[4][4] = {};
        #pragma unroll
        for (int ks = 0; ks < 4; ks++) {
            uint32_t ah[4], al[4];
            uint32_t aoff = (uint32_t)(16 * wm + lb3 * 8 + l7) * STR + ks * 32 + lb4 * 16;
            ldsm4(ah, sb + A_QH + aoff);
            ldsm4(al, sb + A_QL + aoff);
            #pragma unroll
            for (int t = 0; t < 2; t++) {
                uint32_t bh[4], bl[4];
                uint32_t boff = (uint32_t)(32 * wn + t * 16 + lb4 * 8 + l7) * STR + ks * 32 + lb3 * 16;
                ldsm4(bh, sb + A_KH + boff);
                ldsm4(bl, sb + A_KL + boff);
                #pragma unroll
                for (int s2 = 0; s2 < 2; s2++) {
                    const int nt = t * 2 + s2;
                    mma16816(S[nt], ah, &bh[s2 * 2]);
                    mma16816(S[nt], ah, &bl[s2 * 2]);
                    mma16816(S[nt], al, &bh[s2 * 2]);
                }
            }
        }

        const int k0 = kt * 64;
        if (kt == qt) {   // diagonal mask
            #pragma unroll
            for (int nt = 0; nt < 4; nt++)
                #pragma unroll
                for (int k = 0; k < 4; k++) {
                    int row = q0 + rr0 + (k >> 1) * 8;
                    int col = k0 + 32 * wn + nt * 8 + tig * 2 + (k & 1);
                    if (col > row) S[nt][k] = -1e30f;
                }
        }

        // ---- row max (in-warp + cross-warp via SMEM)
        float pm0 = -1e30f, pm1 = -1e30f;
        #pragma unroll
        for (int nt = 0; nt < 4; nt++) {
            pm0 = fmaxf(pm0, fmaxf(S[nt][0], S[nt][1]));
            pm1 = fmaxf(pm1, fmaxf(S[nt][2], S[nt][3]));
        }
        pm0 = fmaxf(pm0, __shfl_xor_sync(~0u, pm0, 1));
        pm0 = fmaxf(pm0, __shfl_xor_sync(~0u, pm0, 2));
        pm1 = fmaxf(pm1, __shfl_xor_sync(~0u, pm1, 1));
        pm1 = fmaxf(pm1, __shfl_xor_sync(~0u, pm1, 2));
        if (tig == 0) { smax[wn * 64 + rr0] = pm0; smax[wn * 64 + rr0 + 8] = pm1; }
        __syncthreads();         // S1 (also: all QK^T reads of K done)

        if (kt + 1 < kt_end) loadK(kt + 1);   // overlap next-K with softmax+PV

        float nm0 = fmaxf(run_m[0], fmaxf(smax[rr0],     smax[64 + rr0]));
        float nm1 = fmaxf(run_m[1], fmaxf(smax[rr0 + 8], smax[64 + rr0 + 8]));
        float al0 = __expf(run_m[0] - nm0);
        float al1 = __expf(run_m[1] - nm1);

        float rs0 = 0.f, rs1 = 0.f;
        #pragma unroll
        for (int nt = 0; nt < 4; nt++) {
            float p0 = __expf(S[nt][0] - nm0), p1 = __expf(S[nt][1] - nm0);
            float p2 = __expf(S[nt][2] - nm1), p3 = __expf(S[nt][3] - nm1);
            rs0 += p0 + p1; rs1 += p2 + p3;
            uint32_t h0, l0, h1, l1;
            split2(p0, p1, h0, l0);
            split2(p2, p3, h1, l1);
            uint32_t cb = (uint32_t)(32 * wn + nt * 8 + tig * 2) * 2;
            *(uint32_t*)(sm + A_PH + rr0 * STR + cb) = h0;
            *(uint32_t*)(sm + A_PL + rr0 * STR + cb) = l0;
            *(uint32_t*)(sm + A_PH + (rr0 + 8) * STR + cb) = h1;
            *(uint32_t*)(sm + A_PL + (rr0 + 8) * STR + cb) = l1;
        }
        rs0 += __shfl_xor_sync(~0u, rs0, 1); rs0 += __shfl_xor_sync(~0u, rs0, 2);
        rs1 += __shfl_xor_sync(~0u, rs1, 1); rs1 += __shfl_xor_sync(~0u, rs1, 2);
        if (tig == 0) { ssum[wn * 64 + rr0] = rs0; ssum[wn * 64 + rr0 + 8] = rs1; }

        if (kt + 1 < kt_end) cp_wait<1>();    // V of this tile arrived (next-K in flight)
        else                 cp_wait<0>();
        __syncthreads();         // S2 (P, sums, V visible)

        run_l[0] = run_l[0] * al0 + ssum[rr0]     + ssum[64 + rr0];
        run_l[1] = run_l[1] * al1 + ssum[rr0 + 8] + ssum[64 + rr0 + 8];
        run_m[0] = nm0; run_m[1] = nm1;
        #pragma unroll
        for (int nt = 0; nt < 4; nt++) {
            O[nt][0] *= al0; O[nt][1] *= al0; O[nt][2] *= al1; O[nt][3] *= al1;
        }

        // ---- O += P V (bf16x3)
        #pragma unroll
        for (int kk = 0; kk < 4; kk++) {
            uint32_t ph[4], pl[4];
            uint32_t aoff = (uint32_t)(16 * wm + lb3 * 8 + l7) * STR + kk * 32 + lb4 * 16;
            ldsm4(ph, sb + A_PH + aoff);
            ldsm4(pl, sb + A_PL + aoff);
            #pragma unroll
            for (int t = 0; t < 2; t++) {
                uint32_t vh[4], vl[4];
                uint32_t boff = (uint32_t)(32 * wn + t * 16 + lb4 * 8 + l7) * STR + kk * 32 + lb3 * 16;
                ldsm4(vh, sb + A_VH + boff);
                ldsm4(vl, sb + A_VL + boff);
                #pragma unroll
                for (int s2 = 0; s2 < 2; s2++) {
                    const int nt = t * 2 + s2;
                    mma16816(O[nt], ph, &vh[s2 * 2]);
                    mma16816(O[nt], ph, &vl[s2 * 2]);
                    mma16816(O[nt], pl, &vh[s2 * 2]);
                }
            }
        }
        __syncthreads();         // S3 (V reads done -> buffer reusable)
        if (kt + 1 < kt_end) loadV(kt + 1);
    }

    // epilogue: unnormalized O + (m, l)
    #pragma unroll
    for (int nt = 0; nt < 4; nt++) {
        int c = 32 * wn + nt * 8 + tig * 2;
        *(float2*)&g_opart[sp][(size_t)orow * H + c]       = make_float2(O[nt][0], O[nt][1]);
        *(float2*)&g_opart[sp][(size_t)(orow + 8) * H + c] = make_float2(O[nt][2], O[nt][3]);
    }
    if (wn == 0 && tig == 0) {
        g_m[sp][orow] = run_m[0]; g_m[sp][orow + 8] = run_m[1];
        g_l[sp][orow] = run_l[0]; g_l[sp][orow + 8] = run_l[1];
    }
}

// ===========================================================================
// Combine the NSPLIT partials
// ===========================================================================
__global__ __launch_bounds__(256) void combine_kernel(float* __restrict__ out)
{
    int idx = blockIdx.x * 256 + threadIdx.x;
    int row = idx >> 4;
    int c4  = (idx & 15) * 4;

    float mv[NSPLIT], lv[NSPLIT];
    float M = -1e30f;
    #pragma unroll
    for (int s = 0; s < NSPLIT; s++) {
        mv[s] = g_m[s][row];
        lv[s] = g_l[s][row];
        M = fmaxf(M, mv[s]);
    }
    float w[NSPLIT], denom = 0.f;
    #pragma unroll
    for (int s = 0; s < NSPLIT; s++) {
        w[s] = __expf(mv[s] - M);
        denom += w[s] * lv[s];
    }
    float inv = 1.0f / denom;

    float4 r = make_float4(0.f, 0.f, 0.f, 0.f);
    #pragma unroll
    for (int s = 0; s < NSPLIT; s++) {
        float4 o = *(const float4*)&g_opart[s][(size_t)row * H + c4];
        r.x += w[s] * o.x; r.y += w[s] * o.y; r.z += w[s] * o.z; r.w += w[s] * o.w;
    }
    r.x *= inv; r.y *= inv; r.z *= inv; r.w *= inv;
    *(float4*)&out[(size_t)row * H + c4] = r;
}

// ===========================================================================
extern "C" void kernel_launch(void* const* d_in, const int* in_sizes, int n_in,
                              void* d_out, int out_size)
{
    const float* x  = (const float*)d_in[0];
    const float* Wq = (const float*)d_in[1];
    const float* Wk = (const float*)d_in[2];
    const float* Wv = (const float*)d_in[3];
    float* out = (float*)d_out;

    cudaFuncSetAttribute(proj_mma_kernel,
                         cudaFuncAttributeMaxDynamicSharedMemorySize, PROJ_SMEM);
    cudaFuncSetAttribute(attn_mma_kernel,
                         cudaFuncAttributeMaxDynamicSharedMemorySize, ATTN_SMEM);

    xconv_kernel<<<(M_TOTAL * C / 4) / 256, 256>>>(x);
    wconv_kernel<<<192, 256>>>(Wq, Wk, Wv);
    proj_mma_kernel<<<M_TOTAL / 64, 256, PROJ_SMEM>>>();
    attn_mma_kernel<<<dim3(T / 64, BATCH, NSPLIT), 256, ATTN_SMEM>>>();
    combine_kernel<<<(M_TOTAL * (H / 4)) / 256, 256>>>(out);
}

// round 8
// speedup vs baseline: 4.0444x; 1.0470x over previous
#include <cuda_runtime.h>
#include <cuda_bf16.h>
#include <cstdint>

#define BATCH 4
#define T 2048
#define C 1024
#define H 64
#define M_TOTAL (BATCH * T)   // 8192
#define NSPLIT 4

// Scratch (allocation-free rule: __device__ globals)
__device__ float g_opart[NSPLIT][BATCH * T * H];
__device__ float g_m[NSPLIT][BATCH * T];
__device__ float g_l[NSPLIT][BATCH * T];
__device__ __nv_bfloat16 g_wh[192 * C];        // [Wq;Wk;Wv] bf16 hi
__device__ __nv_bfloat16 g_wl[192 * C];        // bf16 lo
__device__ __nv_bfloat16 g_qh[M_TOTAL * H];    // q (scale folded) hi/lo
__device__ __nv_bfloat16 g_ql[M_TOTAL * H];
__device__ __nv_bfloat16 g_kh[M_TOTAL * H];
__device__ __nv_bfloat16 g_kl[M_TOTAL * H];
__device__ __nv_bfloat16 g_vth[H * M_TOTAL];   // V transposed [h][m]
__device__ __nv_bfloat16 g_vtl[H * M_TOTAL];

// ===========================================================================
// Helpers (portable sm_80+ tensor path)
// ===========================================================================
__device__ __forceinline__ uint32_t smem_to_u32(const void* p) {
    uint32_t a;
    asm("{ .reg .u64 t; cvta.to.shared.u64 t, %1; cvt.u32.u64 %0, t; }" : "=r"(a) : "l"(p));
    return a;
}
__device__ __forceinline__ void ldsm4(uint32_t* r, uint32_t addr) {
    asm volatile("ldmatrix.sync.aligned.m8n8.x4.shared.b16 {%0,%1,%2,%3}, [%4];"
                 : "=r"(r[0]), "=r"(r[1]), "=r"(r[2]), "=r"(r[3]) : "r"(addr));
}
__device__ __forceinline__ void mma16816(float* d, const uint32_t* a, const uint32_t* b) {
    asm volatile(
        "mma.sync.aligned.m16n8k16.row.col.f32.bf16.bf16.f32 "
        "{%0,%1,%2,%3}, {%4,%5,%6,%7}, {%8,%9}, {%0,%1,%2,%3};"
        : "+f"(d[0]), "+f"(d[1]), "+f"(d[2]), "+f"(d[3])
        : "r"(a[0]), "r"(a[1]), "r"(a[2]), "r"(a[3]), "r"(b[0]), "r"(b[1]));
}
__device__ __forceinline__ void cp16(uint32_t smem_addr, const void* gptr) {
    asm volatile("cp.async.cg.shared.global [%0], [%1], 16;" :: "r"(smem_addr), "l"(gptr));
}
__device__ __forceinline__ void cp_commit() { asm volatile("cp.async.commit_group;" ::: "memory"); }
template <int N>
__device__ __forceinline__ void cp_wait() {
    asm volatile("cp.async.wait_group %0;" :: "n"(N) : "memory");
}

__device__ __forceinline__ void split2(float a, float b, uint32_t& hi, uint32_t& lo) {
    __nv_bfloat16 ha = __float2bfloat16_rn(a);
    __nv_bfloat16 hb = __float2bfloat16_rn(b);
    float ra = a - __bfloat162float(ha);
    float rb = b - __bfloat162float(hb);
    __nv_bfloat16 la = __float2bfloat16_rn(ra);
    __nv_bfloat16 lb = __float2bfloat16_rn(rb);
    hi = (uint32_t)__bfloat16_as_ushort(ha) | ((uint32_t)__bfloat16_as_ushort(hb) << 16);
    lo = (uint32_t)__bfloat16_as_ushort(la) | ((uint32_t)__bfloat16_as_ushort(lb) << 16);
}

// ===========================================================================
// W -> bf16 hi/lo (tiny)
// ===========================================================================
__global__ __launch_bounds__(256) void wconv_kernel(
    const float* __restrict__ Wq, const float* __restrict__ Wk, const float* __restrict__ Wv)
{
    int idx = blockIdx.x * 256 + threadIdx.x;
    int r = idx >> 8;
    int c = idx & 255;
    const float* W = (r < 64) ? Wq : ((r < 128) ? Wk : Wv);
    int rr = r & 63;
    float4 w = *(const float4*)(W + (size_t)rr * C + c * 4);
    uint32_t h0, l0, h1, l1;
    split2(w.x, w.y, h0, l0);
    split2(w.z, w.w, h1, l1);
    *(uint2*)&g_wh[(size_t)r * C + c * 4] = make_uint2(h0, h1);
    *(uint2*)&g_wl[(size_t)r * C + c * 4] = make_uint2(l0, l1);
}

// ===========================================================================
// Projection via mma.sync bf16x3 with FUSED fp32->bf16x2 conversion of x.
// BM=32, N=192 per CTA -> grid 256.  K-chunks of 32, double-buffered,
// ONE __syncthreads per chunk.  8 warps = (wm 0..1) x (wn 0..3, N=48 each).
// Epilogue emits bf16 hi/lo: q (x0.125), k, TRANSPOSED v.
// ===========================================================================
#define PJ_AH 0        // 32 rows x 80 B
#define PJ_AL 2560
#define PJ_BH 5120     // 192 rows x 80 B
#define PJ_BL 20480
#define PJ_BUF 35840
#define PROJ_SMEM (2 * PJ_BUF)
#define NIT 32

__global__ __launch_bounds__(256) void proj_mma_kernel(const float* __restrict__ x)
{
    extern __shared__ char sm[];
    const uint32_t sb = smem_to_u32(sm);
    const int tid  = threadIdx.x;
    const int wid  = tid >> 5;
    const int lane = tid & 31;
    const int mblk = blockIdx.x * 32;

    const int wm = wid >> 2, wn = wid & 3;
    const int mrow = wm * 16, nbase = wn * 48;
    const int l7 = lane & 7, lb3 = (lane >> 3) & 1, lb4 = (lane >> 4) & 1;
    const int g = lane >> 2, tig = lane & 3;

    // A loader: 1 float4 per thread per chunk
    const int arow = tid >> 3;        // 0..31
    const int ac4  = tid & 7;         // float4 within 32-float chunk

    auto issueB = [&](int it) {
        const int k0 = it * 32;
        const uint32_t bo = sb + (it & 1) * PJ_BUF;
        #pragma unroll
        for (int i = 0; i < 3; i++) {
            int idx = i * 256 + tid;
            int r = idx >> 2;         // 0..191
            int c = idx & 3;
            cp16(bo + PJ_BH + r * 80 + c * 16, g_wh + (size_t)r * C + k0 + c * 8);
            cp16(bo + PJ_BL + r * 80 + c * 16, g_wl + (size_t)r * C + k0 + c * 8);
        }
        cp_commit();
    };
    auto stsA = [&](int it, float4 a) {
        char* bo = sm + (it & 1) * PJ_BUF;
        uint32_t h0, l0, h1, l1;
        split2(a.x, a.y, h0, l0);
        split2(a.z, a.w, h1, l1);
        *(uint2*)(bo + PJ_AH + arow * 80 + ac4 * 8) = make_uint2(h0, h1);
        *(uint2*)(bo + PJ_AL + arow * 80 + ac4 * 8) = make_uint2(l0, l1);
    };

    // prologue
    float4 areg = *(const float4*)(x + (size_t)(mblk + arow) * C + ac4 * 4);
    stsA(0, areg);
    issueB(0);

    float acc[6][4] = {};

    for (int it = 0; it < NIT; it++) {
        if (it + 1 < NIT)
            areg = *(const float4*)(x + (size_t)(mblk + arow) * C + (it + 1) * 32 + ac4 * 4);

        cp_wait<0>();
        __syncthreads();            // B(it) + A(it) visible; all prior reads done

        if (it + 1 < NIT) issueB(it + 1);

        const uint32_t bo = sb + (it & 1) * PJ_BUF;
        #pragma unroll
        for (int ks = 0; ks < 2; ks++) {
            const uint32_t aoff = (uint32_t)(mrow + lb3 * 8 + l7) * 80 + ks * 32 + lb4 * 16;
            uint32_t ah[4], al[4];
            ldsm4(ah, bo + PJ_AH + aoff);
            ldsm4(al, bo + PJ_AL + aoff);

            #pragma unroll
            for (int t = 0; t < 3; t++) {
                const uint32_t boff = (uint32_t)(nbase + t * 16 + lb4 * 8 + l7) * 80
                                    + ks * 32 + lb3 * 16;
                uint32_t bh[4], bl[4];
                ldsm4(bh, bo + PJ_BH + boff);
                ldsm4(bl, bo + PJ_BL + boff);
                #pragma unroll
                for (int s2 = 0; s2 < 2; s2++) {
                    const int nt = t * 2 + s2;
                    mma16816(acc[nt], ah, &bh[s2 * 2]);
                    mma16816(acc[nt], ah, &bl[s2 * 2]);
                    mma16816(acc[nt], al, &bh[s2 * 2]);
                }
            }
        }

        if (it + 1 < NIT) stsA(it + 1, areg);   // into buffer q (disjoint from p)
    }

    // epilogue -> bf16 hi/lo globals
    const int m1 = mblk + mrow + g;
    #pragma unroll
    for (int nt = 0; nt < 6; nt++) {
        const int col = nbase + nt * 8 + tig * 2;
        const int j   = col >> 6;
        const int hc  = col & 63;
        if (j == 0) {
            uint32_t h0, l0;
            split2(acc[nt][0] * 0.125f, acc[nt][1] * 0.125f, h0, l0);
            *(uint32_t*)&g_qh[(size_t)m1 * H + hc] = h0;
            *(uint32_t*)&g_ql[(size_t)m1 * H + hc] = l0;
            split2(acc[nt][2] * 0.125f, acc[nt][3] * 0.125f, h0, l0);
            *(uint32_t*)&g_qh[(size_t)(m1 + 8) * H + hc] = h0;
            *(uint32_t*)&g_ql[(size_t)(m1 + 8) * H + hc] = l0;
        } else if (j == 1) {
            uint32_t h0, l0;
            split2(acc[nt][0], acc[nt][1], h0, l0);
            *(uint32_t*)&g_kh[(size_t)m1 * H + hc] = h0;
            *(uint32_t*)&g_kl[(size_t)m1 * H + hc] = l0;
            split2(acc[nt][2], acc[nt][3], h0, l0);
            *(uint32_t*)&g_kh[(size_t)(m1 + 8) * H + hc] = h0;
            *(uint32_t*)&g_kl[(size_t)(m1 + 8) * H + hc] = l0;
        } else {
            #pragma unroll
            for (int k = 0; k < 4; k++) {
                int r  = m1 + (k >> 1) * 8;
                int cc = hc + (k & 1);
                float v = acc[nt][k];
                __nv_bfloat16 hi = __float2bfloat16_rn(v);
                __nv_bfloat16 lo = __float2bfloat16_rn(v - __bfloat162float(hi));
                g_vth[(size_t)cc * M_TOTAL + r] = hi;
                g_vtl[(size_t)cc * M_TOTAL + r] = lo;
            }
        }
    }
}

// ===========================================================================
// Flash attention on mma.sync, bf16x3.  BM=64, BN=64, 8 warps.
// Split-KV over blockIdx.z (NSPLIT=4), heavy-first q-tile order.
// ===========================================================================
#define STR 144                  // SMEM row stride bytes (64 bf16 + 16B pad)
#define A_QH 0
#define A_QL 9216
#define A_KH 18432
#define A_KL 27648
#define A_VH 36864
#define A_VL 46080
#define A_PH 55296
#define A_PL 64512
#define A_MAX 73728              // float[2][64]
#define A_SUM 74240              // float[2][64]
#define ATTN_SMEM 74752

__global__ __launch_bounds__(256) void attn_mma_kernel()
{
    extern __shared__ char sm[];
    const uint32_t sb = smem_to_u32(sm);
    const int tid  = threadIdx.x;
    const int wid  = tid >> 5;
    const int lane = tid & 31;
    const int wm = wid & 3, wn = wid >> 2;
    const int g = lane >> 2, tig = lane & 3;
    const int l7 = lane & 7, lb3 = (lane >> 3) & 1, lb4 = (lane >> 4) & 1;

    const int b  = blockIdx.y;
    const int sp = blockIdx.z;
    const int qt = (T / 64 - 1) - blockIdx.x;   // heavy-first
    const int q0 = qt * 64;
    const int bT = b * T;

    const int ntiles = qt + 1;
    const int kt_beg = (sp * ntiles) >> 2;
    const int kt_end = ((sp + 1) * ntiles) >> 2;

    const int rr0  = 16 * wm + g;
    const int orow = bT + q0 + rr0;

    if (kt_beg >= kt_end) {   // empty split: neutral partials
        #pragma unroll
        for (int nt = 0; nt < 4; nt++) {
            int c = 32 * wn + nt * 8 + tig * 2;
            *(float2*)&g_opart[sp][(size_t)orow * H + c]       = make_float2(0.f, 0.f);
            *(float2*)&g_opart[sp][(size_t)(orow + 8) * H + c] = make_float2(0.f, 0.f);
        }
        if (wn == 0 && tig == 0) {
            g_m[sp][orow] = -1e30f; g_m[sp][orow + 8] = -1e30f;
            g_l[sp][orow] = 0.f;    g_l[sp][orow + 8] = 0.f;
        }
        return;
    }

    auto loadK = [&](int kt) {
        int k0 = kt * 64;
        #pragma unroll
        for (int i = 0; i < 2; i++) {
            int idx = i * 256 + tid, r = idx >> 3, c = idx & 7;
            cp16(sb + A_KH + r * STR + c * 16, g_kh + (size_t)(bT + k0 + r) * H + c * 8);
            cp16(sb + A_KL + r * STR + c * 16, g_kl + (size_t)(bT + k0 + r) * H + c * 8);
        }
        cp_commit();
    };
    auto loadV = [&](int kt) {
        int k0 = kt * 64;
        #pragma unroll
        for (int i = 0; i < 2; i++) {
            int idx = i * 256 + tid, r = idx >> 3, c = idx & 7;   // r = h row
            cp16(sb + A_VH + r * STR + c * 16, g_vth + (size_t)r * M_TOTAL + bT + k0 + c * 8);
            cp16(sb + A_VL + r * STR + c * 16, g_vtl + (size_t)r * M_TOTAL + bT + k0 + c * 8);
        }
        cp_commit();
    };

    // prologue: {Q + K(kt_beg)} group, then {V(kt_beg)} group
    #pragma unroll
    for (int i = 0; i < 2; i++) {
        int idx = i * 256 + tid, r = idx >> 3, c = idx & 7;
        cp16(sb + A_QH + r * STR + c * 16, g_qh + (size_t)(bT + q0 + r) * H + c * 8);
        cp16(sb + A_QL + r * STR + c * 16, g_ql + (size_t)(bT + q0 + r) * H + c * 8);
    }
    loadK(kt_beg);
    loadV(kt_beg);

    float O[4][4] = {};
    float run_m[2] = {-1e30f, -1e30f};
    float run_l[2] = {0.f, 0.f};
    float* smax = (float*)(sm + A_MAX);
    float* ssum = (float*)(sm + A_SUM);

    for (int kt = kt_beg; kt < kt_end; kt++) {
        cp_wait<1>();            // Q+K of this tile arrived
        __syncthreads();         // S0

        // ---- S = Q K^T (bf16x3)
        float S[4][4] = {};
        #pragma unroll
        for (int ks = 0; ks < 4; ks++) {
            uint32_t ah[4], al[4];
            uint32_t aoff = (uint32_t)(16 * wm + lb3 * 8 + l7) * STR + ks * 32 + lb4 * 16;
            ldsm4(ah, sb + A_QH + aoff);
            ldsm4(al, sb + A_QL + aoff);
            #pragma unroll
            for (int t = 0; t < 2; t++) {
                uint32_t bh[4], bl[4];
                uint32_t boff = (uint32_t)(32 * wn + t * 16 + lb4 * 8 + l7) * STR + ks * 32 + lb3 * 16;
                ldsm4(bh, sb + A_KH + boff);
                ldsm4(bl, sb + A_KL + boff);
                #pragma unroll
                for (int s2 = 0; s2 < 2; s2++) {
                    const int nt = t * 2 + s2;
                    mma16816(S[nt], ah, &bh[s2 * 2]);
                    mma16816(S[nt], ah, &bl[s2 * 2]);
                    mma16816(S[nt], al, &bh[s2 * 2]);
                }
            }
        }

        const int k0 = kt * 64;
        if (kt == qt) {   // diagonal mask
            #pragma unroll
            for (int nt = 0; nt < 4; nt++)
                #pragma unroll
                for (int k = 0; k < 4; k++) {
                    int row = q0 + rr0 + (k >> 1) * 8;
                    int col = k0 + 32 * wn + nt * 8 + tig * 2 + (k & 1);
                    if (col > row) S[nt][k] = -1e30f;
                }
        }

        // ---- row max (in-warp + cross-warp via SMEM)
        float pm0 = -1e30f, pm1 = -1e30f;
        #pragma unroll
        for (int nt = 0; nt < 4; nt++) {
            pm0 = fmaxf(pm0, fmaxf(S[nt][0], S[nt][1]));
            pm1 = fmaxf(pm1, fmaxf(S[nt][2], S[nt][3]));
        }
        pm0 = fmaxf(pm0, __shfl_xor_sync(~0u, pm0, 1));
        pm0 = fmaxf(pm0, __shfl_xor_sync(~0u, pm0, 2));
        pm1 = fmaxf(pm1, __shfl_xor_sync(~0u, pm1, 1));
        pm1 = fmaxf(pm1, __shfl_xor_sync(~0u, pm1, 2));
        if (tig == 0) { smax[wn * 64 + rr0] = pm0; smax[wn * 64 + rr0 + 8] = pm1; }
        __syncthreads();         // S1 (also: all QK^T reads of K done)

        if (kt + 1 < kt_end) loadK(kt + 1);   // overlap next-K with softmax+PV

        float nm0 = fmaxf(run_m[0], fmaxf(smax[rr0],     smax[64 + rr0]));
        float nm1 = fmaxf(run_m[1], fmaxf(smax[rr0 + 8], smax[64 + rr0 + 8]));
        float al0 = __expf(run_m[0] - nm0);
        float al1 = __expf(run_m[1] - nm1);

        float rs0 = 0.f, rs1 = 0.f;
        #pragma unroll
        for (int nt = 0; nt < 4; nt++) {
            float p0 = __expf(S[nt][0] - nm0), p1 = __expf(S[nt][1] - nm0);
            float p2 = __expf(S[nt][2] - nm1), p3 = __expf(S[nt][3] - nm1);
            rs0 += p0 + p1; rs1 += p2 + p3;
            uint32_t h0, l0, h1, l1;
            split2(p0, p1, h0, l0);
            split2(p2, p3, h1, l1);
            uint32_t cb = (uint32_t)(32 * wn + nt * 8 + tig * 2) * 2;
            *(uint32_t*)(sm + A_PH + rr0 * STR + cb) = h0;
            *(uint32_t*)(sm + A_PL + rr0 * STR + cb) = l0;
            *(uint32_t*)(sm + A_PH + (rr0 + 8) * STR + cb) = h1;
            *(uint32_t*)(sm + A_PL + (rr0 + 8) * STR + cb) = l1;
        }
        rs0 += __shfl_xor_sync(~0u, rs0, 1); rs0 += __shfl_xor_sync(~0u, rs0, 2);
        rs1 += __shfl_xor_sync(~0u, rs1, 1); rs1 += __shfl_xor_sync(~0u, rs1, 2);
        if (tig == 0) { ssum[wn * 64 + rr0] = rs0; ssum[wn * 64 + rr0 + 8] = rs1; }

        if (kt + 1 < kt_end) cp_wait<1>();    // V of this tile arrived (next-K in flight)
        else                 cp_wait<0>();
        __syncthreads();         // S2 (P, sums, V visible)

        run_l[0] = run_l[0] * al0 + ssum[rr0]     + ssum[64 + rr0];
        run_l[1] = run_l[1] * al1 + ssum[rr0 + 8] + ssum[64 + rr0 + 8];
        run_m[0] = nm0; run_m[1] = nm1;
        #pragma unroll
        for (int nt = 0; nt < 4; nt++) {
            O[nt][0] *= al0; O[nt][1] *= al0; O[nt][2] *= al1; O[nt][3] *= al1;
        }

        // ---- O += P V (bf16x3)
        #pragma unroll
        for (int kk = 0; kk < 4; kk++) {
            uint32_t ph[4], pl[4];
            uint32_t aoff = (uint32_t)(16 * wm + lb3 * 8 + l7) * STR + kk * 32 + lb4 * 16;
            ldsm4(ph, sb + A_PH + aoff);
            ldsm4(pl, sb + A_PL + aoff);
            #pragma unroll
            for (int t = 0; t < 2; t++) {
                uint32_t vh[4], vl[4];
                uint32_t boff = (uint32_t)(32 * wn + t * 16 + lb4 * 8 + l7) * STR + kk * 32 + lb3 * 16;
                ldsm4(vh, sb + A_VH + boff);
                ldsm4(vl, sb + A_VL + boff);
                #pragma unroll
                for (int s2 = 0; s2 < 2; s2++) {
                    const int nt = t * 2 + s2;
                    mma16816(O[nt], ph, &vh[s2 * 2]);
                    mma16816(O[nt], ph, &vl[s2 * 2]);
                    mma16816(O[nt], pl, &vh[s2 * 2]);
                }
            }
        }
        __syncthreads();         // S3 (V reads done -> buffer reusable)
        if (kt + 1 < kt_end) loadV(kt + 1);
    }

    // epilogue: unnormalized O + (m, l)
    #pragma unroll
    for (int nt = 0; nt < 4; nt++) {
        int c = 32 * wn + nt * 8 + tig * 2;
        *(float2*)&g_opart[sp][(size_t)orow * H + c]       = make_float2(O[nt][0], O[nt][1]);
        *(float2*)&g_opart[sp][(size_t)(orow + 8) * H + c] = make_float2(O[nt][2], O[nt][3]);
    }
    if (wn == 0 && tig == 0) {
        g_m[sp][orow] = run_m[0]; g_m[sp][orow + 8] = run_m[1];
        g_l[sp][orow] = run_l[0]; g_l[sp][orow + 8] = run_l[1];
    }
}

// ===========================================================================
// Combine the NSPLIT partials
// ===========================================================================
__global__ __launch_bounds__(256) void combine_kernel(float* __restrict__ out)
{
    int idx = blockIdx.x * 256 + threadIdx.x;
    int row = idx >> 4;
    int c4  = (idx & 15) * 4;

    float mv[NSPLIT], lv[NSPLIT];
    float M = -1e30f;
    #pragma unroll
    for (int s = 0; s < NSPLIT; s++) {
        mv[s] = g_m[s][row];
        lv[s] = g_l[s][row];
        M = fmaxf(M, mv[s]);
    }
    float w[NSPLIT], denom = 0.f;
    #pragma unroll
    for (int s = 0; s < NSPLIT; s++) {
        w[s] = __expf(mv[s] - M);
        denom += w[s] * lv[s];
    }
    float inv = 1.0f / denom;

    float4 r = make_float4(0.f, 0.f, 0.f, 0.f);
    #pragma unroll
    for (int s = 0; s < NSPLIT; s++) {
        float4 o = *(const float4*)&g_opart[s][(size_t)row * H + c4];
        r.x += w[s] * o.x; r.y += w[s] * o.y; r.z += w[s] * o.z; r.w += w[s] * o.w;
    }
    r.x *= inv; r.y *= inv; r.z *= inv; r.w *= inv;
    *(float4*)&out[(size_t)row * H + c4] = r;
}

// ===========================================================================
extern "C" void kernel_launch(void* const* d_in, const int* in_sizes, int n_in,
                              void* d_out, int out_size)
{
    const float* x  = (const float*)d_in[0];
    const float* Wq = (const float*)d_in[1];
    const float* Wk = (const float*)d_in[2];
    const float* Wv = (const float*)d_in[3];
    float* out = (float*)d_out;

    cudaFuncSetAttribute(proj_mma_kernel,
                         cudaFuncAttributeMaxDynamicSharedMemorySize, PROJ_SMEM);
    cudaFuncSetAttribute(attn_mma_kernel,
                         cudaFuncAttributeMaxDynamicSharedMemorySize, ATTN_SMEM);

    wconv_kernel<<<192, 256>>>(Wq, Wk, Wv);
    proj_mma_kernel<<<M_TOTAL / 32, 256, PROJ_SMEM>>>(x);
    attn_mma_kernel<<<dim3(T / 64, BATCH, NSPLIT), 256, ATTN_SMEM>>>();
    combine_kernel<<<(M_TOTAL * (H / 4)) / 256, 256>>>(out);
}

// round 9
// speedup vs baseline: 4.2453x; 1.0497x over previous
#include <cuda_runtime.h>
#include <cuda_bf16.h>
#include <cstdint>

#define BATCH 4
#define T 2048
#define C 1024
#define H 64
#define M_TOTAL (BATCH * T)   // 8192
#define NSPLIT 4

// Scratch (allocation-free rule: __device__ globals)
__device__ float g_opart[NSPLIT][BATCH * T * H];
__device__ float g_m[NSPLIT][BATCH * T];
__device__ float g_l[NSPLIT][BATCH * T];
__device__ __nv_bfloat16 g_wh[192 * C];        // [Wq;Wk;Wv] bf16 hi
__device__ __nv_bfloat16 g_wl[192 * C];        // bf16 lo
__device__ __nv_bfloat16 g_qh[M_TOTAL * H];    // q (scale folded) hi/lo
__device__ __nv_bfloat16 g_ql[M_TOTAL * H];
__device__ __nv_bfloat16 g_kh[M_TOTAL * H];
__device__ __nv_bfloat16 g_kl[M_TOTAL * H];
__device__ __nv_bfloat16 g_vth[H * M_TOTAL];   // V transposed [h][m]
__device__ __nv_bfloat16 g_vtl[H * M_TOTAL];

// ===========================================================================
// Helpers (portable sm_80+ tensor path)
// ===========================================================================
__device__ __forceinline__ uint32_t smem_to_u32(const void* p) {
    uint32_t a;
    asm("{ .reg .u64 t; cvta.to.shared.u64 t, %1; cvt.u32.u64 %0, t; }" : "=r"(a) : "l"(p));
    return a;
}
__device__ __forceinline__ void ldsm4(uint32_t* r, uint32_t addr) {
    asm volatile("ldmatrix.sync.aligned.m8n8.x4.shared.b16 {%0,%1,%2,%3}, [%4];"
                 : "=r"(r[0]), "=r"(r[1]), "=r"(r[2]), "=r"(r[3]) : "r"(addr));
}
__device__ __forceinline__ void mma16816(float* d, const uint32_t* a, const uint32_t* b) {
    asm volatile(
        "mma.sync.aligned.m16n8k16.row.col.f32.bf16.bf16.f32 "
        "{%0,%1,%2,%3}, {%4,%5,%6,%7}, {%8,%9}, {%0,%1,%2,%3};"
        : "+f"(d[0]), "+f"(d[1]), "+f"(d[2]), "+f"(d[3])
        : "r"(a[0]), "r"(a[1]), "r"(a[2]), "r"(a[3]), "r"(b[0]), "r"(b[1]));
}
__device__ __forceinline__ void cp16(uint32_t smem_addr, const void* gptr) {
    asm volatile("cp.async.cg.shared.global [%0], [%1], 16;" :: "r"(smem_addr), "l"(gptr));
}
__device__ __forceinline__ void cp_commit() { asm volatile("cp.async.commit_group;" ::: "memory"); }
template <int N>
__device__ __forceinline__ void cp_wait() {
    asm volatile("cp.async.wait_group %0;" :: "n"(N) : "memory");
}

__device__ __forceinline__ void split2(float a, float b, uint32_t& hi, uint32_t& lo) {
    __nv_bfloat16 ha = __float2bfloat16_rn(a);
    __nv_bfloat16 hb = __float2bfloat16_rn(b);
    float ra = a - __bfloat162float(ha);
    float rb = b - __bfloat162float(hb);
    __nv_bfloat16 la = __float2bfloat16_rn(ra);
    __nv_bfloat16 lb = __float2bfloat16_rn(rb);
    hi = (uint32_t)__bfloat16_as_ushort(ha) | ((uint32_t)__bfloat16_as_ushort(hb) << 16);
    lo = (uint32_t)__bfloat16_as_ushort(la) | ((uint32_t)__bfloat16_as_ushort(lb) << 16);
}

// ===========================================================================
// W -> bf16 hi/lo (tiny)
// ===========================================================================
__global__ __launch_bounds__(256) void wconv_kernel(
    const float* __restrict__ Wq, const float* __restrict__ Wk, const float* __restrict__ Wv)
{
    int idx = blockIdx.x * 256 + threadIdx.x;
    int r = idx >> 8;
    int c = idx & 255;
    const float* W = (r < 64) ? Wq : ((r < 128) ? Wk : Wv);
    int rr = r & 63;
    float4 w = *(const float4*)(W + (size_t)rr * C + c * 4);
    uint32_t h0, l0, h1, l1;
    split2(w.x, w.y, h0, l0);
    split2(w.z, w.w, h1, l1);
    *(uint2*)&g_wh[(size_t)r * C + c * 4] = make_uint2(h0, h1);
    *(uint2*)&g_wl[(size_t)r * C + c * 4] = make_uint2(l0, l1);
}

// ===========================================================================
// Projection via mma.sync bf16x3 with FUSED fp32->bf16x2 conversion of x.
// BM=64, N=192 per CTA -> grid 128.  K-chunks of 32, double-buffered,
// ONE __syncthreads per chunk.  8 warps = (wm 0..3 m-tiles) x (wn 0..1, N=96).
// Epilogue emits bf16 hi/lo: q (x0.125), k, TRANSPOSED v.
// ===========================================================================
#define PJ_AH 0        // 64 rows x 80 B
#define PJ_AL 5120
#define PJ_BH 10240    // 192 rows x 80 B
#define PJ_BL 25600
#define PJ_BUF 40960
#define PROJ_SMEM (2 * PJ_BUF)
#define NIT 32

__global__ __launch_bounds__(256) void proj_mma_kernel(const float* __restrict__ x)
{
    extern __shared__ char sm[];
    const uint32_t sb = smem_to_u32(sm);
    const int tid  = threadIdx.x;
    const int wid  = tid >> 5;
    const int lane = tid & 31;
    const int mblk = blockIdx.x * 64;

    const int wm = wid & 3, wn = wid >> 2;
    const int mrow = wm * 16, nbase = wn * 96;
    const int l7 = lane & 7, lb3 = (lane >> 3) & 1, lb4 = (lane >> 4) & 1;
    const int g = lane >> 2, tig = lane & 3;

    // A loader: 2 float4 per thread per chunk (64 rows x 8 f4)
    const int arow = tid >> 2;            // 0..63  (idx>>3 with i*256: rows split below)
    // use idx = i*256+tid: row = idx>>3 (0..63), c4 = idx&7

    auto issueB = [&](int it) {
        const int k0 = it * 32;
        const uint32_t bo = sb + (it & 1) * PJ_BUF;
        #pragma unroll
        for (int i = 0; i < 3; i++) {
            int idx = i * 256 + tid;
            int r = idx >> 2;             // 0..191
            int c = idx & 3;
            cp16(bo + PJ_BH + r * 80 + c * 16, g_wh + (size_t)r * C + k0 + c * 8);
            cp16(bo + PJ_BL + r * 80 + c * 16, g_wl + (size_t)r * C + k0 + c * 8);
        }
        cp_commit();
    };
    auto ldA = [&](int it, float4* areg) {
        const int k0 = it * 32;
        #pragma unroll
        for (int i = 0; i < 2; i++) {
            int idx = i * 256 + tid;
            int row = idx >> 3, c4 = idx & 7;
            areg[i] = *(const float4*)(x + (size_t)(mblk + row) * C + k0 + c4 * 4);
        }
    };
    auto stsA = [&](int it, const float4* areg) {
        char* bo = sm + (it & 1) * PJ_BUF;
        #pragma unroll
        for (int i = 0; i < 2; i++) {
            int idx = i * 256 + tid;
            int row = idx >> 3, c4 = idx & 7;
            uint32_t h0, l0, h1, l1;
            split2(areg[i].x, areg[i].y, h0, l0);
            split2(areg[i].z, areg[i].w, h1, l1);
            *(uint2*)(bo + PJ_AH + row * 80 + c4 * 8) = make_uint2(h0, h1);
            *(uint2*)(bo + PJ_AL + row * 80 + c4 * 8) = make_uint2(l0, l1);
        }
    };

    // prologue
    float4 areg[2];
    ldA(0, areg);
    stsA(0, areg);
    issueB(0);

    float acc[12][4] = {};

    for (int it = 0; it < NIT; it++) {
        if (it + 1 < NIT) ldA(it + 1, areg);

        cp_wait<0>();
        __syncthreads();            // B(it) + A(it) visible; all prior reads done

        if (it + 1 < NIT) issueB(it + 1);

        const uint32_t bo = sb + (it & 1) * PJ_BUF;
        #pragma unroll
        for (int ks = 0; ks < 2; ks++) {
            const uint32_t aoff = (uint32_t)(mrow + lb3 * 8 + l7) * 80 + ks * 32 + lb4 * 16;
            uint32_t ah[4], al[4];
            ldsm4(ah, bo + PJ_AH + aoff);
            ldsm4(al, bo + PJ_AL + aoff);

            #pragma unroll
            for (int t = 0; t < 6; t++) {
                const uint32_t boff = (uint32_t)(nbase + t * 16 + lb4 * 8 + l7) * 80
                                    + ks * 32 + lb3 * 16;
                uint32_t bh[4], bl[4];
                ldsm4(bh, bo + PJ_BH + boff);
                ldsm4(bl, bo + PJ_BL + boff);
                #pragma unroll
                for (int s2 = 0; s2 < 2; s2++) {
                    const int nt = t * 2 + s2;
                    mma16816(acc[nt], ah, &bh[s2 * 2]);
                    mma16816(acc[nt], ah, &bl[s2 * 2]);
                    mma16816(acc[nt], al, &bh[s2 * 2]);
                }
            }
        }

        if (it + 1 < NIT) stsA(it + 1, areg);   // into buffer q (disjoint from p)
    }

    // epilogue -> bf16 hi/lo globals
    const int m1 = mblk + mrow + g;
    #pragma unroll
    for (int nt = 0; nt < 12; nt++) {
        const int col = nbase + nt * 8 + tig * 2;
        const int j   = col >> 6;
        const int hc  = col & 63;
        if (j == 0) {
            uint32_t h0, l0;
            split2(acc[nt][0] * 0.125f, acc[nt][1] * 0.125f, h0, l0);
            *(uint32_t*)&g_qh[(size_t)m1 * H + hc] = h0;
            *(uint32_t*)&g_ql[(size_t)m1 * H + hc] = l0;
            split2(acc[nt][2] * 0.125f, acc[nt][3] * 0.125f, h0, l0);
            *(uint32_t*)&g_qh[(size_t)(m1 + 8) * H + hc] = h0;
            *(uint32_t*)&g_ql[(size_t)(m1 + 8) * H + hc] = l0;
        } else if (j == 1) {
            uint32_t h0, l0;
            split2(acc[nt][0], acc[nt][1], h0, l0);
            *(uint32_t*)&g_kh[(size_t)m1 * H + hc] = h0;
            *(uint32_t*)&g_kl[(size_t)m1 * H + hc] = l0;
            split2(acc[nt][2], acc[nt][3], h0, l0);
            *(uint32_t*)&g_kh[(size_t)(m1 + 8) * H + hc] = h0;
            *(uint32_t*)&g_kl[(size_t)(m1 + 8) * H + hc] = l0;
        } else {
            #pragma unroll
            for (int k = 0; k < 4; k++) {
                int r  = m1 + (k >> 1) * 8;
                int cc = hc + (k & 1);
                float v = acc[nt][k];
                __nv_bfloat16 hi = __float2bfloat16_rn(v);
                __nv_bfloat16 lo = __float2bfloat16_rn(v - __bfloat162float(hi));
                g_vth[(size_t)cc * M_TOTAL + r] = hi;
                g_vtl[(size_t)cc * M_TOTAL + r] = lo;
            }
        }
    }
}

// ===========================================================================
// Flash attention on mma.sync, bf16x3.  BM=64, BN=64, 8 warps.
// Split-KV over blockIdx.z (NSPLIT=4), heavy-first q-tile order.
// ===========================================================================
#define STR 144                  // SMEM row stride bytes (64 bf16 + 16B pad)
#define A_QH 0
#define A_QL 9216
#define A_KH 18432
#define A_KL 27648
#define A_VH 36864
#define A_VL 46080
#define A_PH 55296
#define A_PL 64512
#define A_MAX 73728              // float[2][64]
#define A_SUM 74240              // float[2][64]
#define ATTN_SMEM 74752

__global__ __launch_bounds__(256) void attn_mma_kernel()
{
    extern __shared__ char sm[];
    const uint32_t sb = smem_to_u32(sm);
    const int tid  = threadIdx.x;
    const int wid  = tid >> 5;
    const int lane = tid & 31;
    const int wm = wid & 3, wn = wid >> 2;
    const int g = lane >> 2, tig = lane & 3;
    const int l7 = lane & 7, lb3 = (lane >> 3) & 1, lb4 = (lane >> 4) & 1;

    const int b  = blockIdx.y;
    const int sp = blockIdx.z;
    const int qt = (T / 64 - 1) - blockIdx.x;   // heavy-first
    const int q0 = qt * 64;
    const int bT = b * T;

    const int ntiles = qt + 1;
    const int kt_beg = (sp * ntiles) >> 2;
    const int kt_end = ((sp + 1) * ntiles) >> 2;

    const int rr0  = 16 * wm + g;
    const int orow = bT + q0 + rr0;

    if (kt_beg >= kt_end) {   // empty split: neutral partials
        #pragma unroll
        for (int nt = 0; nt < 4; nt++) {
            int c = 32 * wn + nt * 8 + tig * 2;
            *(float2*)&g_opart[sp][(size_t)orow * H + c]       = make_float2(0.f, 0.f);
            *(float2*)&g_opart[sp][(size_t)(orow + 8) * H + c] = make_float2(0.f, 0.f);
        }
        if (wn == 0 && tig == 0) {
            g_m[sp][orow] = -1e30f; g_m[sp][orow + 8] = -1e30f;
            g_l[sp][orow] = 0.f;    g_l[sp][orow + 8] = 0.f;
        }
        return;
    }

    auto loadK = [&](int kt) {
        int k0 = kt * 64;
        #pragma unroll
        for (int i = 0; i < 2; i++) {
            int idx = i * 256 + tid, r = idx >> 3, c = idx & 7;
            cp16(sb + A_KH + r * STR + c * 16, g_kh + (size_t)(bT + k0 + r) * H + c * 8);
            cp16(sb + A_KL + r * STR + c * 16, g_kl + (size_t)(bT + k0 + r) * H + c * 8);
        }
        cp_commit();
    };
    auto loadV = [&](int kt) {
        int k0 = kt * 64;
        #pragma unroll
        for (int i = 0; i < 2; i++) {
            int idx = i * 256 + tid, r = idx >> 3, c = idx & 7;   // r = h row
            cp16(sb + A_VH + r * STR + c * 16, g_vth + (size_t)r * M_TOTAL + bT + k0 + c * 8);
            cp16(sb + A_VL + r * STR + c * 16, g_vtl + (size_t)r * M_TOTAL + bT + k0 + c * 8);
        }
        cp_commit();
    };

    // prologue: {Q + K(kt_beg)} group, then {V(kt_beg)} group
    #pragma unroll
    for (int i = 0; i < 2; i++) {
        int idx = i * 256 + tid, r = idx >> 3, c = idx & 7;
        cp16(sb + A_QH + r * STR + c * 16, g_qh + (size_t)(bT + q0 + r) * H + c * 8);
        cp16(sb + A_QL + r * STR + c * 16, g_ql + (size_t)(bT + q0 + r) * H + c * 8);
    }
    loadK(kt_beg);
    loadV(kt_beg);

    float O[4][4] = {};
    float run_m[2] = {-1e30f, -1e30f};
    float run_l[2] = {0.f, 0.f};
    float* smax = (float*)(sm + A_MAX);
    float* ssum = (float*)(sm + A_SUM);

    for (int kt = kt_beg; kt < kt_end; kt++) {
        cp_wait<1>();            // Q+K of this tile arrived
        __syncthreads();         // S0

        // ---- S = Q K^T (bf16x3)
        float S[4][4] = {};
        #pragma unroll
        for (int ks = 0; ks < 4; ks++) {
            uint32_t ah[4], al[4];
            uint32_t aoff = (uint32_t)(16 * wm + lb3 * 8 + l7) * STR + ks * 32 + lb4 * 16;
            ldsm4(ah, sb + A_QH + aoff);
            ldsm4(al, sb + A_QL + aoff);
            #pragma unroll
            for (int t = 0; t < 2; t++) {
                uint32_t bh[4], bl[4];
                uint32_t boff = (uint32_t)(32 * wn + t * 16 + lb4 * 8 + l7) * STR + ks * 32 + lb3 * 16;
                ldsm4(bh, sb + A_KH + boff);
                ldsm4(bl, sb + A_KL + boff);
                #pragma unroll
                for (int s2 = 0; s2 < 2; s2++) {
                    const int nt = t * 2 + s2;
                    mma16816(S[nt], ah, &bh[s2 * 2]);
                    mma16816(S[nt], ah, &bl[s2 * 2]);
                    mma16816(S[nt], al, &bh[s2 * 2]);
                }
            }
        }

        const int k0 = kt * 64;
        if (kt == qt) {   // diagonal mask
            #pragma unroll
            for (int nt = 0; nt < 4; nt++)
                #pragma unroll
                for (int k = 0; k < 4; k++) {
                    int row = q0 + rr0 + (k >> 1) * 8;
                    int col = k0 + 32 * wn + nt * 8 + tig * 2 + (k & 1);
                    if (col > row) S[nt][k] = -1e30f;
                }
        }

        // ---- row max (in-warp + cross-warp via SMEM)
        float pm0 = -1e30f, pm1 = -1e30f;
        #pragma unroll
        for (int nt = 0; nt < 4; nt++) {
            pm0 = fmaxf(pm0, fmaxf(S[nt][0], S[nt][1]));
            pm1 = fmaxf(pm1, fmaxf(S[nt][2], S[nt][3]));
        }
        pm0 = fmaxf(pm0, __shfl_xor_sync(~0u, pm0, 1));
        pm0 = fmaxf(pm0, __shfl_xor_sync(~0u, pm0, 2));
        pm1 = fmaxf(pm1, __shfl_xor_sync(~0u, pm1, 1));
        pm1 = fmaxf(pm1, __shfl_xor_sync(~0u, pm1, 2));
        if (tig == 0) { smax[wn * 64 + rr0] = pm0; smax[wn * 64 + rr0 + 8] = pm1; }
        __syncthreads();         // S1 (also: all QK^T reads of K done)

        if (kt + 1 < kt_end) loadK(kt + 1);   // overlap next-K with softmax+PV

        float nm0 = fmaxf(run_m[0], fmaxf(smax[rr0],     smax[64 + rr0]));
        float nm1 = fmaxf(run_m[1], fmaxf(smax[rr0 + 8], smax[64 + rr0 + 8]));
        float al0 = __expf(run_m[0] - nm0);
        float al1 = __expf(run_m[1] - nm1);

        float rs0 = 0.f, rs1 = 0.f;
        #pragma unroll
        for (int nt = 0; nt < 4; nt++) {
            float p0 = __expf(S[nt][0] - nm0), p1 = __expf(S[nt][1] - nm0);
            float p2 = __expf(S[nt][2] - nm1), p3 = __expf(S[nt][3] - nm1);
            rs0 += p0 + p1; rs1 += p2 + p3;
            uint32_t h0, l0, h1, l1;
            split2(p0, p1, h0, l0);
            split2(p2, p3, h1, l1);
            uint32_t cb = (uint32_t)(32 * wn + nt * 8 + tig * 2) * 2;
            *(uint32_t*)(sm + A_PH + rr0 * STR + cb) = h0;
            *(uint32_t*)(sm + A_PL + rr0 * STR + cb) = l0;
            *(uint32_t*)(sm + A_PH + (rr0 + 8) * STR + cb) = h1;
            *(uint32_t*)(sm + A_PL + (rr0 + 8) * STR + cb) = l1;
        }
        rs0 += __shfl_xor_sync(~0u, rs0, 1); rs0 += __shfl_xor_sync(~0u, rs0, 2);
        rs1 += __shfl_xor_sync(~0u, rs1, 1); rs1 += __shfl_xor_sync(~0u, rs1, 2);
        if (tig == 0) { ssum[wn * 64 + rr0] = rs0; ssum[wn * 64 + rr0 + 8] = rs1; }

        if (kt + 1 < kt_end) cp_wait<1>();    // V of this tile arrived (next-K in flight)
        else                 cp_wait<0>();
        __syncthreads();         // S2 (P, sums, V visible)

        run_l[0] = run_l[0] * al0 + ssum[rr0]     + ssum[64 + rr0];
        run_l[1] = run_l[1] * al1 + ssum[rr0 + 8] + ssum[64 + rr0 + 8];
        run_m[0] = nm0; run_m[1] = nm1;
        #pragma unroll
        for (int nt = 0; nt < 4; nt++) {
            O[nt][0] *= al0; O[nt][1] *= al0; O[nt][2] *= al1; O[nt][3] *= al1;
        }

        // ---- O += P V (bf16x3)
        #pragma unroll
        for (int kk = 0; kk < 4; kk++) {
            uint32_t ph[4], pl[4];
            uint32_t aoff = (uint32_t)(16 * wm + lb3 * 8 + l7) * STR + kk * 32 + lb4 * 16;
            ldsm4(ph, sb + A_PH + aoff);
            ldsm4(pl, sb + A_PL + aoff);
            #pragma unroll
            for (int t = 0; t < 2; t++) {
                uint32_t vh[4], vl[4];
                uint32_t boff = (uint32_t)(32 * wn + t * 16 + lb4 * 8 + l7) * STR + kk * 32 + lb3 * 16;
                ldsm4(vh, sb + A_VH + boff);
                ldsm4(vl, sb + A_VL + boff);
                #pragma unroll
                for (int s2 = 0; s2 < 2; s2++) {
                    const int nt = t * 2 + s2;
                    mma16816(O[nt], ph, &vh[s2 * 2]);
                    mma16816(O[nt], ph, &vl[s2 * 2]);
                    mma16816(O[nt], pl, &vh[s2 * 2]);
                }
            }
        }
        __syncthreads();         // S3 (V reads done -> buffer reusable)
        if (kt + 1 < kt_end) loadV(kt + 1);
    }

    // epilogue: unnormalized O + (m, l)
    #pragma unroll
    for (int nt = 0; nt < 4; nt++) {
        int c = 32 * wn + nt * 8 + tig * 2;
        *(float2*)&g_opart[sp][(size_t)orow * H + c]       = make_float2(O[nt][0], O[nt][1]);
        *(float2*)&g_opart[sp][(size_t)(orow + 8) * H + c] = make_float2(O[nt][2], O[nt][3]);
    }
    if (wn == 0 && tig == 0) {
        g_m[sp][orow] = run_m[0]; g_m[sp][orow + 8] = run_m[1];
        g_l[sp][orow] = run_l[0]; g_l[sp][orow + 8] = run_l[1];
    }
}

// ===========================================================================
// Combine the NSPLIT partials
// ===========================================================================
__global__ __launch_bounds__(256) void combine_kernel(float* __restrict__ out)
{
    int idx = blockIdx.x * 256 + threadIdx.x;
    int row = idx >> 4;
    int c4  = (idx & 15) * 4;

    float mv[NSPLIT], lv[NSPLIT];
    float M = -1e30f;
    #pragma unroll
    for (int s = 0; s < NSPLIT; s++) {
        mv[s] = g_m[s][row];
        lv[s] = g_l[s][row];
        M = fmaxf(M, mv[s]);
    }
    float w[NSPLIT], denom = 0.f;
    #pragma unroll
    for (int s = 0; s < NSPLIT; s++) {
        w[s] = __expf(mv[s] - M);
        denom += w[s] * lv[s];
    }
    float inv = 1.0f / denom;

    float4 r = make_float4(0.f, 0.f, 0.f, 0.f);
    #pragma unroll
    for (int s = 0; s < NSPLIT; s++) {
        float4 o = *(const float4*)&g_opart[s][(size_t)row * H + c4];
        r.x += w[s] * o.x; r.y += w[s] * o.y; r.z += w[s] * o.z; r.w += w[s] * o.w;
    }
    r.x *= inv; r.y *= inv; r.z *= inv; r.w *= inv;
    *(float4*)&out[(size_t)row * H + c4] = r;
}

// ===========================================================================
extern "C" void kernel_launch(void* const* d_in, const int* in_sizes, int n_in,
                              void* d_out, int out_size)
{
    const float* x  = (const float*)d_in[0];
    const float* Wq = (const float*)d_in[1];
    const float* Wk = (const float*)d_in[2];
    const float* Wv = (const float*)d_in[3];
    float* out = (float*)d_out;

    cudaFuncSetAttribute(proj_mma_kernel,
                         cudaFuncAttributeMaxDynamicSharedMemorySize, PROJ_SMEM);
    cudaFuncSetAttribute(attn_mma_kernel,
                         cudaFuncAttributeMaxDynamicSharedMemorySize, ATTN_SMEM);

    wconv_kernel<<<192, 256>>>(Wq, Wk, Wv);
    proj_mma_kernel<<<M_TOTAL / 64, 256, PROJ_SMEM>>>(x);
    attn_mma_kernel<<<dim3(T / 64, BATCH, NSPLIT), 256, ATTN_SMEM>>>();
    combine_kernel<<<(M_TOTAL * (H / 4)) / 256, 256>>>(out);
}

// round 10
// speedup vs baseline: 4.5892x; 1.0810x over previous
#include <cuda_runtime.h>
#include <cuda_bf16.h>
#include <cstdint>

#define BATCH 4
#define T 2048
#define C 1024
#define H 64
#define M_TOTAL (BATCH * T)   // 8192
#define NSPLIT 4

// Scratch (allocation-free rule: __device__ globals)
__device__ float g_opart[NSPLIT][BATCH * T * H];
__device__ float g_m[NSPLIT][BATCH * T];
__device__ float g_l[NSPLIT][BATCH * T];
__device__ __nv_bfloat16 g_wh[192 * C];        // [Wq;Wk;Wv] bf16 hi
__device__ __nv_bfloat16 g_wl[192 * C];        // bf16 lo
__device__ __nv_bfloat16 g_qh[M_TOTAL * H];    // q (scale folded) hi/lo
__device__ __nv_bfloat16 g_ql[M_TOTAL * H];
__device__ __nv_bfloat16 g_kh[M_TOTAL * H];
__device__ __nv_bfloat16 g_kl[M_TOTAL * H];
__device__ __nv_bfloat16 g_vth[H * M_TOTAL];   // V transposed [h][m]
__device__ __nv_bfloat16 g_vtl[H * M_TOTAL];

// ===========================================================================
// Helpers (portable sm_80+ tensor path)
// ===========================================================================
__device__ __forceinline__ uint32_t smem_to_u32(const void* p) {
    uint32_t a;
    asm("{ .reg .u64 t; cvta.to.shared.u64 t, %1; cvt.u32.u64 %0, t; }" : "=r"(a) : "l"(p));
    return a;
}
__device__ __forceinline__ void ldsm4(uint32_t* r, uint32_t addr) {
    asm volatile("ldmatrix.sync.aligned.m8n8.x4.shared.b16 {%0,%1,%2,%3}, [%4];"
                 : "=r"(r[0]), "=r"(r[1]), "=r"(r[2]), "=r"(r[3]) : "r"(addr));
}
__device__ __forceinline__ void mma16816(float* d, const uint32_t* a, const uint32_t* b) {
    asm volatile(
        "mma.sync.aligned.m16n8k16.row.col.f32.bf16.bf16.f32 "
        "{%0,%1,%2,%3}, {%4,%5,%6,%7}, {%8,%9}, {%0,%1,%2,%3};"
        : "+f"(d[0]), "+f"(d[1]), "+f"(d[2]), "+f"(d[3])
        : "r"(a[0]), "r"(a[1]), "r"(a[2]), "r"(a[3]), "r"(b[0]), "r"(b[1]));
}
__device__ __forceinline__ void cp16(uint32_t smem_addr, const void* gptr) {
    asm volatile("cp.async.cg.shared.global [%0], [%1], 16;" :: "r"(smem_addr), "l"(gptr));
}
__device__ __forceinline__ void cp_commit() { asm volatile("cp.async.commit_group;" ::: "memory"); }
template <int N>
__device__ __forceinline__ void cp_wait() {
    asm volatile("cp.async.wait_group %0;" :: "n"(N) : "memory");
}

__device__ __forceinline__ void split2(float a, float b, uint32_t& hi, uint32_t& lo) {
    __nv_bfloat16 ha = __float2bfloat16_rn(a);
    __nv_bfloat16 hb = __float2bfloat16_rn(b);
    float ra = a - __bfloat162float(ha);
    float rb = b - __bfloat162float(hb);
    __nv_bfloat16 la = __float2bfloat16_rn(ra);
    __nv_bfloat16 lb = __float2bfloat16_rn(rb);
    hi = (uint32_t)__bfloat16_as_ushort(ha) | ((uint32_t)__bfloat16_as_ushort(hb) << 16);
    lo = (uint32_t)__bfloat16_as_ushort(la) | ((uint32_t)__bfloat16_as_ushort(lb) << 16);
}

// ===========================================================================
// W -> bf16 hi/lo (tiny)
// ===========================================================================
__global__ __launch_bounds__(256) void wconv_kernel(
    const float* __restrict__ Wq, const float* __restrict__ Wk, const float* __restrict__ Wv)
{
    int idx = blockIdx.x * 256 + threadIdx.x;
    int r = idx >> 8;
    int c = idx & 255;
    const float* W = (r < 64) ? Wq : ((r < 128) ? Wk : Wv);
    int rr = r & 63;
    float4 w = *(const float4*)(W + (size_t)rr * C + c * 4);
    uint32_t h0, l0, h1, l1;
    split2(w.x, w.y, h0, l0);
    split2(w.z, w.w, h1, l1);
    *(uint2*)&g_wh[(size_t)r * C + c * 4] = make_uint2(h0, h1);
    *(uint2*)&g_wl[(size_t)r * C + c * 4] = make_uint2(l0, l1);
}

// ===========================================================================
// Projection via mma.sync bf16x3 with FUSED fp32->bf16x2 conversion of x.
// BM=64, BN=96 per CTA -> grid (128, 2) = 256 CTAs, 4/SM SMEM capacity.
// N-split keeps W L2 traffic constant; x re-read hits L2 (32 MB < 126 MB).
// K-chunks of 32, double-buffered, ONE __syncthreads per chunk.
// 8 warps = (wm 0..3 m-tiles) x (wn 0..1, N=48 each).
// Epilogue emits bf16 hi/lo: q (x0.125), k, TRANSPOSED v.
// ===========================================================================
#define PJ_AH 0        // 64 rows x 80 B
#define PJ_AL 5120
#define PJ_BH 10240    // 96 rows x 80 B
#define PJ_BL 17920
#define PJ_BUF 25600
#define PROJ_SMEM (2 * PJ_BUF)
#define NIT 32

__global__ __launch_bounds__(256) void proj_mma_kernel(const float* __restrict__ x)
{
    extern __shared__ char sm[];
    const uint32_t sb = smem_to_u32(sm);
    const int tid  = threadIdx.x;
    const int wid  = tid >> 5;
    const int lane = tid & 31;
    const int mblk   = blockIdx.x * 64;
    const int nhalf  = blockIdx.y;         // 0 or 1 -> W rows [96*nhalf, +96)
    const int wrow0  = nhalf * 96;

    const int wm = wid & 3, wn = wid >> 2;
    const int mrow = wm * 16;
    const int nloc = wn * 48;              // local n within the 96
    const int l7 = lane & 7, lb3 = (lane >> 3) & 1, lb4 = (lane >> 4) & 1;
    const int g = lane >> 2, tig = lane & 3;

    auto issueB = [&](int it) {
        const int k0 = it * 32;
        const uint32_t bo = sb + (it & 1) * PJ_BUF;
        #pragma unroll
        for (int i = 0; i < 2; i++) {
            int idx = i * 256 + tid;
            if (idx < 384) {
                int r = idx >> 2;          // 0..95 local row
                int c = idx & 3;
                cp16(bo + PJ_BH + r * 80 + c * 16, g_wh + (size_t)(wrow0 + r) * C + k0 + c * 8);
                cp16(bo + PJ_BL + r * 80 + c * 16, g_wl + (size_t)(wrow0 + r) * C + k0 + c * 8);
            }
        }
        cp_commit();
    };
    auto ldA = [&](int it, float4* areg) {
        const int k0 = it * 32;
        #pragma unroll
        for (int i = 0; i < 2; i++) {
            int idx = i * 256 + tid;
            int row = idx >> 3, c4 = idx & 7;
            areg[i] = *(const float4*)(x + (size_t)(mblk + row) * C + k0 + c4 * 4);
        }
    };
    auto stsA = [&](int it, const float4* areg) {
        char* bo = sm + (it & 1) * PJ_BUF;
        #pragma unroll
        for (int i = 0; i < 2; i++) {
            int idx = i * 256 + tid;
            int row = idx >> 3, c4 = idx & 7;
            uint32_t h0, l0, h1, l1;
            split2(areg[i].x, areg[i].y, h0, l0);
            split2(areg[i].z, areg[i].w, h1, l1);
            *(uint2*)(bo + PJ_AH + row * 80 + c4 * 8) = make_uint2(h0, h1);
            *(uint2*)(bo + PJ_AL + row * 80 + c4 * 8) = make_uint2(l0, l1);
        }
    };

    // prologue
    float4 areg[2];
    ldA(0, areg);
    stsA(0, areg);
    issueB(0);

    float acc[6][4] = {};

    for (int it = 0; it < NIT; it++) {
        if (it + 1 < NIT) ldA(it + 1, areg);

        cp_wait<0>();
        __syncthreads();            // B(it) + A(it) visible; all prior reads done

        if (it + 1 < NIT) issueB(it + 1);

        const uint32_t bo = sb + (it & 1) * PJ_BUF;
        #pragma unroll
        for (int ks = 0; ks < 2; ks++) {
            const uint32_t aoff = (uint32_t)(mrow + lb3 * 8 + l7) * 80 + ks * 32 + lb4 * 16;
            uint32_t ah[4], al[4];
            ldsm4(ah, bo + PJ_AH + aoff);
            ldsm4(al, bo + PJ_AL + aoff);

            #pragma unroll
            for (int t = 0; t < 3; t++) {
                const uint32_t boff = (uint32_t)(nloc + t * 16 + lb4 * 8 + l7) * 80
                                    + ks * 32 + lb3 * 16;
                uint32_t bh[4], bl[4];
                ldsm4(bh, bo + PJ_BH + boff);
                ldsm4(bl, bo + PJ_BL + boff);
                #pragma unroll
                for (int s2 = 0; s2 < 2; s2++) {
                    const int nt = t * 2 + s2;
                    mma16816(acc[nt], ah, &bh[s2 * 2]);
                    mma16816(acc[nt], ah, &bl[s2 * 2]);
                    mma16816(acc[nt], al, &bh[s2 * 2]);
                }
            }
        }

        if (it + 1 < NIT) stsA(it + 1, areg);   // into buffer q (disjoint from p)
    }

    // epilogue -> bf16 hi/lo globals
    const int m1 = mblk + mrow + g;
    #pragma unroll
    for (int nt = 0; nt < 6; nt++) {
        const int col = wrow0 + nloc + nt * 8 + tig * 2;   // global col in [0,192)
        const int j   = col >> 6;
        const int hc  = col & 63;
        if (j == 0) {
            uint32_t h0, l0;
            split2(acc[nt][0] * 0.125f, acc[nt][1] * 0.125f, h0, l0);
            *(uint32_t*)&g_qh[(size_t)m1 * H + hc] = h0;
            *(uint32_t*)&g_ql[(size_t)m1 * H + hc] = l0;
            split2(acc[nt][2] * 0.125f, acc[nt][3] * 0.125f, h0, l0);
            *(uint32_t*)&g_qh[(size_t)(m1 + 8) * H + hc] = h0;
            *(uint32_t*)&g_ql[(size_t)(m1 + 8) * H + hc] = l0;
        } else if (j == 1) {
            uint32_t h0, l0;
            split2(acc[nt][0], acc[nt][1], h0, l0);
            *(uint32_t*)&g_kh[(size_t)m1 * H + hc] = h0;
            *(uint32_t*)&g_kl[(size_t)m1 * H + hc] = l0;
            split2(acc[nt][2], acc[nt][3], h0, l0);
            *(uint32_t*)&g_kh[(size_t)(m1 + 8) * H + hc] = h0;
            *(uint32_t*)&g_kl[(size_t)(m1 + 8) * H + hc] = l0;
        } else {
            #pragma unroll
            for (int k = 0; k < 4; k++) {
                int r  = m1 + (k >> 1) * 8;
                int cc = hc + (k & 1);
                float v = acc[nt][k];
                __nv_bfloat16 hi = __float2bfloat16_rn(v);
                __nv_bfloat16 lo = __float2bfloat16_rn(v - __bfloat162float(hi));
                g_vth[(size_t)cc * M_TOTAL + r] = hi;
                g_vtl[(size_t)cc * M_TOTAL + r] = lo;
            }
        }
    }
}

// ===========================================================================
// Flash attention on mma.sync, bf16x3.  BM=64, BN=64, 8 warps.
// Split-KV over blockIdx.z (NSPLIT=4), heavy-first q-tile order.
// ===========================================================================
#define STR 144                  // SMEM row stride bytes (64 bf16 + 16B pad)
#define A_QH 0
#define A_QL 9216
#define A_KH 18432
#define A_KL 27648
#define A_VH 36864
#define A_VL 46080
#define A_PH 55296
#define A_PL 64512
#define A_MAX 73728              // float[2][64]
#define A_SUM 74240              // float[2][64]
#define ATTN_SMEM 74752

__global__ __launch_bounds__(256) void attn_mma_kernel()
{
    extern __shared__ char sm[];
    const uint32_t sb = smem_to_u32(sm);
    const int tid  = threadIdx.x;
    const int wid  = tid >> 5;
    const int lane = tid & 31;
    const int wm = wid & 3, wn = wid >> 2;
    const int g = lane >> 2, tig = lane & 3;
    const int l7 = lane & 7, lb3 = (lane >> 3) & 1, lb4 = (lane >> 4) & 1;

    const int b  = blockIdx.y;
    const int sp = blockIdx.z;
    const int qt = (T / 64 - 1) - blockIdx.x;   // heavy-first
    const int q0 = qt * 64;
    const int bT = b * T;

    const int ntiles = qt + 1;
    const int kt_beg = (sp * ntiles) >> 2;
    const int kt_end = ((sp + 1) * ntiles) >> 2;

    const int rr0  = 16 * wm + g;
    const int orow = bT + q0 + rr0;

    if (kt_beg >= kt_end) {   // empty split: neutral partials
        #pragma unroll
        for (int nt = 0; nt < 4; nt++) {
            int c = 32 * wn + nt * 8 + tig * 2;
            *(float2*)&g_opart[sp][(size_t)orow * H + c]       = make_float2(0.f, 0.f);
            *(float2*)&g_opart[sp][(size_t)(orow + 8) * H + c] = make_float2(0.f, 0.f);
        }
        if (wn == 0 && tig == 0) {
            g_m[sp][orow] = -1e30f; g_m[sp][orow + 8] = -1e30f;
            g_l[sp][orow] = 0.f;    g_l[sp][orow + 8] = 0.f;
        }
        return;
    }

    auto loadK = [&](int kt) {
        int k0 = kt * 64;
        #pragma unroll
        for (int i = 0; i < 2; i++) {
            int idx = i * 256 + tid, r = idx >> 3, c = idx & 7;
            cp16(sb + A_KH + r * STR + c * 16, g_kh + (size_t)(bT + k0 + r) * H + c * 8);
            cp16(sb + A_KL + r * STR + c * 16, g_kl + (size_t)(bT + k0 + r) * H + c * 8);
        }
        cp_commit();
    };
    auto loadV = [&](int kt) {
        int k0 = kt * 64;
        #pragma unroll
        for (int i = 0; i < 2; i++) {
            int idx = i * 256 + tid, r = idx >> 3, c = idx & 7;   // r = h row
            cp16(sb + A_VH + r * STR + c * 16, g_vth + (size_t)r * M_TOTAL + bT + k0 + c * 8);
            cp16(sb + A_VL + r * STR + c * 16, g_vtl + (size_t)r * M_TOTAL + bT + k0 + c * 8);
        }
        cp_commit();
    };

    // prologue: {Q + K(kt_beg)} group, then {V(kt_beg)} group
    #pragma unroll
    for (int i = 0; i < 2; i++) {
        int idx = i * 256 + tid, r = idx >> 3, c = idx & 7;
        cp16(sb + A_QH + r * STR + c * 16, g_qh + (size_t)(bT + q0 + r) * H + c * 8);
        cp16(sb + A_QL + r * STR + c * 16, g_ql + (size_t)(bT + q0 + r) * H + c * 8);
    }
    loadK(kt_beg);
    loadV(kt_beg);

    float O[4][4] = {};
    float run_m[2] = {-1e30f, -1e30f};
    float run_l[2] = {0.f, 0.f};
    float* smax = (float*)(sm + A_MAX);
    float* ssum = (float*)(sm + A_SUM);

    for (int kt = kt_beg; kt < kt_end; kt++) {
        cp_wait<1>();            // Q+K of this tile arrived
        __syncthreads();         // S0

        // ---- S = Q K^T (bf16x3)
        float S[4][4] = {};
        #pragma unroll
        for (int ks = 0; ks < 4; ks++) {
            uint32_t ah[4], al[4];
            uint32_t aoff = (uint32_t)(16 * wm + lb3 * 8 + l7) * STR + ks * 32 + lb4 * 16;
            ldsm4(ah, sb + A_QH + aoff);
            ldsm4(al, sb + A_QL + aoff);
            #pragma unroll
            for (int t = 0; t < 2; t++) {
                uint32_t bh[4], bl[4];
                uint32_t boff = (uint32_t)(32 * wn + t * 16 + lb4 * 8 + l7) * STR + ks * 32 + lb3 * 16;
                ldsm4(bh, sb + A_KH + boff);
                ldsm4(bl, sb + A_KL + boff);
                #pragma unroll
                for (int s2 = 0; s2 < 2; s2++) {
                    const int nt = t * 2 + s2;
                    mma16816(S[nt], ah, &bh[s2 * 2]);
                    mma16816(S[nt], ah, &bl[s2 * 2]);
                    mma16816(S[nt], al, &bh[s2 * 2]);
                }
            }
        }

        const int k0 = kt * 64;
        if (kt == qt) {   // diagonal mask
            #pragma unroll
            for (int nt = 0; nt < 4; nt++)
                #pragma unroll
                for (int k = 0; k < 4; k++) {
                    int row = q0 + rr0 + (k >> 1) * 8;
                    int col = k0 + 32 * wn + nt * 8 + tig * 2 + (k & 1);
                    if (col > row) S[nt][k] = -1e30f;
                }
        }

        // ---- row max (in-warp + cross-warp via SMEM)
        float pm0 = -1e30f, pm1 = -1e30f;
        #pragma unroll
        for (int nt = 0; nt < 4; nt++) {
            pm0 = fmaxf(pm0, fmaxf(S[nt][0], S[nt][1]));
            pm1 = fmaxf(pm1, fmaxf(S[nt][2], S[nt][3]));
        }
        pm0 = fmaxf(pm0, __shfl_xor_sync(~0u, pm0, 1));
        pm0 = fmaxf(pm0, __shfl_xor_sync(~0u, pm0, 2));
        pm1 = fmaxf(pm1, __shfl_xor_sync(~0u, pm1, 1));
        pm1 = fmaxf(pm1, __shfl_xor_sync(~0u, pm1, 2));
        if (tig == 0) { smax[wn * 64 + rr0] = pm0; smax[wn * 64 + rr0 + 8] = pm1; }
        __syncthreads();         // S1 (also: all QK^T reads of K done)

        if (kt + 1 < kt_end) loadK(kt + 1);   // overlap next-K with softmax+PV

        float nm0 = fmaxf(run_m[0], fmaxf(smax[rr0],     smax[64 + rr0]));
        float nm1 = fmaxf(run_m[1], fmaxf(smax[rr0 + 8], smax[64 + rr0 + 8]));
        float al0 = __expf(run_m[0] - nm0);
        float al1 = __expf(run_m[1] - nm1);

        float rs0 = 0.f, rs1 = 0.f;
        #pragma unroll
        for (int nt = 0; nt < 4; nt++) {
            float p0 = __expf(S[nt][0] - nm0), p1 = __expf(S[nt][1] - nm0);
            float p2 = __expf(S[nt][2] - nm1), p3 = __expf(S[nt][3] - nm1);
            rs0 += p0 + p1; rs1 += p2 + p3;
            uint32_t h0, l0, h1, l1;
            split2(p0, p1, h0, l0);
            split2(p2, p3, h1, l1);
            uint32_t cb = (uint32_t)(32 * wn + nt * 8 + tig * 2) * 2;
            *(uint32_t*)(sm + A_PH + rr0 * STR + cb) = h0;
            *(uint32_t*)(sm + A_PL + rr0 * STR + cb) = l0;
            *(uint32_t*)(sm + A_PH + (rr0 + 8) * STR + cb) = h1;
            *(uint32_t*)(sm + A_PL + (rr0 + 8) * STR + cb) = l1;
        }
        rs0 += __shfl_xor_sync(~0u, rs0, 1); rs0 += __shfl_xor_sync(~0u, rs0, 2);
        rs1 += __shfl_xor_sync(~0u, rs1, 1); rs1 += __shfl_xor_sync(~0u, rs1, 2);
        if (tig == 0) { ssum[wn * 64 + rr0] = rs0; ssum[wn * 64 + rr0 + 8] = rs1; }

        if (kt + 1 < kt_end) cp_wait<1>();    // V of this tile arrived (next-K in flight)
        else                 cp_wait<0>();
        __syncthreads();         // S2 (P, sums, V visible)

        run_l[0] = run_l[0] * al0 + ssum[rr0]     + ssum[64 + rr0];
        run_l[1] = run_l[1] * al1 + ssum[rr0 + 8] + ssum[64 + rr0 + 8];
        run_m[0] = nm0; run_m[1] = nm1;
        #pragma unroll
        for (int nt = 0; nt < 4; nt++) {
            O[nt][0] *= al0; O[nt][1] *= al0; O[nt][2] *= al1; O[nt][3] *= al1;
        }

        // ---- O += P V (bf16x3)
        #pragma unroll
        for (int kk = 0; kk < 4; kk++) {
            uint32_t ph[4], pl[4];
            uint32_t aoff = (uint32_t)(16 * wm + lb3 * 8 + l7) * STR + kk * 32 + lb4 * 16;
            ldsm4(ph, sb + A_PH + aoff);
            ldsm4(pl, sb + A_PL + aoff);
            #pragma unroll
            for (int t = 0; t < 2; t++) {
                uint32_t vh[4], vl[4];
                uint32_t boff = (uint32_t)(32 * wn + t * 16 + lb4 * 8 + l7) * STR + kk * 32 + lb3 * 16;
                ldsm4(vh, sb + A_VH + boff);
                ldsm4(vl, sb + A_VL + boff);
                #pragma unroll
                for (int s2 = 0; s2 < 2; s2++) {
                    const int nt = t * 2 + s2;
                    mma16816(O[nt], ph, &vh[s2 * 2]);
                    mma16816(O[nt], ph, &vl[s2 * 2]);
                    mma16816(O[nt], pl, &vh[s2 * 2]);
                }
            }
        }
        __syncthreads();         // S3 (V reads done -> buffer reusable)
        if (kt + 1 < kt_end) loadV(kt + 1);
    }

    // epilogue: unnormalized O + (m, l)
    #pragma unroll
    for (int nt = 0; nt < 4; nt++) {
        int c = 32 * wn + nt * 8 + tig * 2;
        *(float2*)&g_opart[sp][(size_t)orow * H + c]       = make_float2(O[nt][0], O[nt][1]);
        *(float2*)&g_opart[sp][(size_t)(orow + 8) * H + c] = make_float2(O[nt][2], O[nt][3]);
    }
    if (wn == 0 && tig == 0) {
        g_m[sp][orow] = run_m[0]; g_m[sp][orow + 8] = run_m[1];
        g_l[sp][orow] = run_l[0]; g_l[sp][orow + 8] = run_l[1];
    }
}

// ===========================================================================
// Combine the NSPLIT partials
// ===========================================================================
__global__ __launch_bounds__(256) void combine_kernel(float* __restrict__ out)
{
    int idx = blockIdx.x * 256 + threadIdx.x;
    int row = idx >> 4;
    int c4  = (idx & 15) * 4;

    float mv[NSPLIT], lv[NSPLIT];
    float M = -1e30f;
    #pragma unroll
    for (int s = 0; s < NSPLIT; s++) {
        mv[s] = g_m[s][row];
        lv[s] = g_l[s][row];
        M = fmaxf(M, mv[s]);
    }
    float w[NSPLIT], denom = 0.f;
    #pragma unroll
    for (int s = 0; s < NSPLIT; s++) {
        w[s] = __expf(mv[s] - M);
        denom += w[s] * lv[s];
    }
    float inv = 1.0f / denom;

    float4 r = make_float4(0.f, 0.f, 0.f, 0.f);
    #pragma unroll
    for (int s = 0; s < NSPLIT; s++) {
        float4 o = *(const float4*)&g_opart[s][(size_t)row * H + c4];
        r.x += w[s] * o.x; r.y += w[s] * o.y; r.z += w[s] * o.z; r.w += w[s] * o.w;
    }
    r.x *= inv; r.y *= inv; r.z *= inv; r.w *= inv;
    *(float4*)&out[(size_t)row * H + c4] = r;
}

// ===========================================================================
extern "C" void kernel_launch(void* const* d_in, const int* in_sizes, int n_in,
                              void* d_out, int out_size)
{
    const float* x  = (const float*)d_in[0];
    const float* Wq = (const float*)d_in[1];
    const float* Wk = (const float*)d_in[2];
    const float* Wv = (const float*)d_in[3];
    float* out = (float*)d_out;

    cudaFuncSetAttribute(proj_mma_kernel,
                         cudaFuncAttributeMaxDynamicSharedMemorySize, PROJ_SMEM);
    cudaFuncSetAttribute(attn_mma_kernel,
                         cudaFuncAttributeMaxDynamicSharedMemorySize, ATTN_SMEM);

    wconv_kernel<<<192, 256>>>(Wq, Wk, Wv);
    proj_mma_kernel<<<dim3(M_TOTAL / 64, 2), 256, PROJ_SMEM>>>(x);
    attn_mma_kernel<<<dim3(T / 64, BATCH, NSPLIT), 256, ATTN_SMEM>>>();
    combine_kernel<<<(M_TOTAL * (H / 4)) / 256, 256>>>(out);
}